// round 4
// baseline (speedup 1.0000x reference)
#include <cuda_runtime.h>
#include <cstdint>
#include <cstdio>

#define B_  4
#define T_  256
#define U_  128
#define EH_ 512
#define PH_ 320
#define JH_ 512
#define NC_ 1025

// ---------------------------------------------------------------------------
// scratch (no cudaMalloc allowed)
// ---------------------------------------------------------------------------
__device__ float g_e[B_ * T_ * JH_];     // [b*T+t][512]  e + b_enc
__device__ float g_p[B_ * U_ * JH_];     // [b*U+u][512]  p + b_pred
__device__ float g_wp[JH_ * 1024];       // W_out cols 0..1023, stride 1024
__device__ float g_wl[JH_];              // W_out col 1024

// ---------------------------------------------------------------------------
// small helpers
// ---------------------------------------------------------------------------
__device__ __forceinline__ void mma_tf32(float* c, const unsigned* a, const unsigned* b) {
    asm volatile(
        "mma.sync.aligned.m16n8k8.row.col.f32.tf32.tf32.f32 "
        "{%0,%1,%2,%3},{%4,%5,%6,%7},{%8,%9},{%0,%1,%2,%3};\n"
        : "+f"(c[0]), "+f"(c[1]), "+f"(c[2]), "+f"(c[3])
        : "r"(a[0]), "r"(a[1]), "r"(a[2]), "r"(a[3]), "r"(b[0]), "r"(b[1]));
}

__device__ __forceinline__ void cpa16(uint32_t dst, const void* src) {
    asm volatile("cp.async.ca.shared.global [%0], [%1], 16;\n" :: "r"(dst), "l"(src));
}
__device__ __forceinline__ void cpa_commit() { asm volatile("cp.async.commit_group;\n"); }
__device__ __forceinline__ void cpa_wait1() { asm volatile("cp.async.wait_group 1;\n"); }
__device__ __forceinline__ void cpa_wait0() { asm volatile("cp.async.wait_group 0;\n"); }

// ---------------------------------------------------------------------------
// projection: O[row][j] = sum_h X[b][h][t] * W[h][j] + bias[j]
// X: [B_, H, L], rows = b*L + t, O: [rows][512]
// ---------------------------------------------------------------------------
__global__ void __launch_bounds__(256)
proj_kernel(const float* __restrict__ X, const float* __restrict__ W,
            const float* __restrict__ bias, float* __restrict__ O,
            int L, int H) {
    __shared__ float Xs[16][64];
    __shared__ float Ws[16][64];
    int tid = threadIdx.x;
    int tc = tid & 15, tr = tid >> 4;
    int j0 = blockIdx.x * 64;
    int row0 = blockIdx.y * 64;
    int b = row0 / L;
    int t0 = row0 % L;

    float acc[4][4];
#pragma unroll
    for (int i = 0; i < 4; i++)
#pragma unroll
        for (int j = 0; j < 4; j++) acc[i][j] = 0.f;

    for (int k0 = 0; k0 < H; k0 += 16) {
#pragma unroll
        for (int i = 0; i < 4; i++) {
            int idx = tid + i * 256;
            int ky = idx >> 6, xx = idx & 63;
            Xs[ky][xx] = X[(size_t)(b * H + k0 + ky) * L + t0 + xx];
            Ws[ky][xx] = W[(size_t)(k0 + ky) * JH_ + j0 + xx];
        }
        __syncthreads();
#pragma unroll
        for (int k = 0; k < 16; k++) {
            float a[4], w[4];
#pragma unroll
            for (int i = 0; i < 4; i++) { a[i] = Xs[k][tr * 4 + i]; w[i] = Ws[k][tc * 4 + i]; }
#pragma unroll
            for (int i = 0; i < 4; i++)
#pragma unroll
                for (int j = 0; j < 4; j++) acc[i][j] += a[i] * w[j];
        }
        __syncthreads();
    }
#pragma unroll
    for (int i = 0; i < 4; i++)
#pragma unroll
        for (int j = 0; j < 4; j++) {
            int col = j0 + tc * 4 + j;
            O[(size_t)(row0 + tr * 4 + i) * JH_ + col] = acc[i][j] + bias[col];
        }
}

// ---------------------------------------------------------------------------
// pack W_out: cols 0..1023 -> g_wp (stride 1024), col 1024 -> g_wl
// ---------------------------------------------------------------------------
__global__ void pack_kernel(const float* __restrict__ W_out) {
    int idx = blockIdx.x * 256 + threadIdx.x;
    if (idx < JH_ * 1024) {
        int j = idx >> 10, c = idx & 1023;
        g_wp[idx] = W_out[(size_t)j * NC_ + c];
    }
    if (idx < JH_) g_wl[idx] = W_out[(size_t)idx * NC_ + 1024];
}

// ---------------------------------------------------------------------------
// joint kernel
// block: 8 t x 8 u = 64 rows, full K=512 A-panel in smem (tf32),
// N in 8 chunks of 128, col 1024 scalar, fused online log-softmax.
// ---------------------------------------------------------------------------
#define AS_STR 516
#define BS_STR 136
#define BS_BUF (32 * BS_STR)             // 4352 floats per buffer
#define SM_BS  (64 * AS_STR)             // 33024
#define SM_WL  (SM_BS + 2 * BS_BUF)      // 41728
#define SM_M   (SM_WL + 512)             // 42240
#define SM_S   (SM_M + 64)               // 42304
#define SM_PM  (SM_S + 64)               // 42368  [4][64]
#define SM_PS  (SM_PM + 256)             // 42624  [4][64]
#define SM_LSE (SM_PS + 256)             // 42880
#define SM_TOT (SM_LSE + 64)             // 42944 floats = 171776 bytes

__device__ __forceinline__ void load_bchunk(float* sm, int buf, int kbase, int n0, int tid) {
    uint32_t dbase = (uint32_t)__cvta_generic_to_shared(sm + SM_BS + buf * BS_BUF);
    const float* src = g_wp + (size_t)kbase * 1024 + n0;
#pragma unroll
    for (int i = 0; i < 4; i++) {
        int idx = tid + i * 256;
        int kr = idx >> 5, c4 = idx & 31;
        cpa16(dbase + (uint32_t)(kr * BS_STR + c4 * 4) * 4, src + (size_t)kr * 1024 + c4 * 4);
    }
}

__global__ void __launch_bounds__(256, 1)
joint_kernel(const float* __restrict__ b_out, float* __restrict__ out) {
    extern __shared__ float sm[];
    int tid = threadIdx.x;
    int lane = tid & 31, warp = tid >> 5;
    int wm = warp & 1, wn = warp >> 1;        // warp grid 2 (m) x 4 (n)
    int m_base = wm * 32, n_base = wn * 32;
    int q = lane >> 2, cg = lane & 3;
    int u0 = blockIdx.x * 8, t0 = blockIdx.y * 8, b = blockIdx.z;

    if (tid < 64) { sm[SM_M + tid] = -1e30f; sm[SM_S + tid] = 0.f; }

    // build A panel: As[r][j] = tf32( relu(e[t][j] + p[u][j]) ), r = ti*8 + uj
    for (int i = tid; i < 64 * 512; i += 256) {
        int r = i >> 9, j = i & 511;
        float e = g_e[((size_t)(b * T_ + t0 + (r >> 3)) << 9) + j];
        float p = g_p[((size_t)(b * U_ + u0 + (r & 7)) << 9) + j];
        float v = fmaxf(e + p, 0.f);
        unsigned uu;
        asm("cvt.rna.tf32.f32 %0, %1;" : "=r"(uu) : "f"(v));
        sm[r * AS_STR + j] = __uint_as_float(uu);
    }
    for (int i = tid; i < 512; i += 256) sm[SM_WL + i] = g_wl[i];
    __syncthreads();

    const unsigned* Au = (const unsigned*)sm;

    // per-thread global row pointers: rows = m_base + mt*16 + h*8 + q
    float* rowp[2][2];
#pragma unroll
    for (int mt = 0; mt < 2; mt++)
#pragma unroll
        for (int h = 0; h < 2; h++) {
            int r = m_base + mt * 16 + h * 8 + q;
            int t = t0 + (r >> 3), u = u0 + (r & 7);
            rowp[mt][h] = out + (size_t)((b * T_ + t) * U_ + u) * NC_;
        }

    for (int nc = 0; nc < 8; nc++) {
        int n0 = nc * 128;
        float acc[2][4][4];
#pragma unroll
        for (int mt = 0; mt < 2; mt++)
#pragma unroll
            for (int nt = 0; nt < 4; nt++)
#pragma unroll
                for (int i = 0; i < 4; i++) acc[mt][nt][i] = 0.f;

        load_bchunk(sm, 0, 0, n0, tid);
        cpa_commit();

        for (int kc = 0; kc < 16; kc++) {
            if (kc < 15) {
                load_bchunk(sm, (kc + 1) & 1, (kc + 1) * 32, n0, tid);
                cpa_commit();
                cpa_wait1();
            } else {
                cpa_wait0();
            }
            __syncthreads();
            const unsigned* Bu = (const unsigned*)(sm + SM_BS + (kc & 1) * BS_BUF);
#pragma unroll
            for (int k8 = 0; k8 < 4; k8++) {
                int acol = kc * 32 + k8 * 8 + cg;
                unsigned a[2][4];
#pragma unroll
                for (int mt = 0; mt < 2; mt++) {
                    const unsigned* ap = Au + (m_base + mt * 16 + q) * AS_STR + acol;
                    a[mt][0] = ap[0];
                    a[mt][1] = ap[8 * AS_STR];
                    a[mt][2] = ap[4];
                    a[mt][3] = ap[8 * AS_STR + 4];
                }
                const unsigned* bp = Bu + (k8 * 8 + cg) * BS_STR + n_base + q;
#pragma unroll
                for (int nt = 0; nt < 4; nt++) {
                    unsigned bb[2];
                    bb[0] = bp[nt * 8];
                    bb[1] = bp[4 * BS_STR + nt * 8];
                    mma_tf32(acc[0][nt], a[0], bb);
                    mma_tf32(acc[1][nt], a[1], bb);
                }
            }
            __syncthreads();
        }

        // ---- epilogue: bias, online softmax stats from registers, store logits
        float bias[8];
#pragma unroll
        for (int nt = 0; nt < 4; nt++) {
            bias[nt * 2]     = __ldg(b_out + n0 + n_base + nt * 8 + 2 * cg);
            bias[nt * 2 + 1] = __ldg(b_out + n0 + n_base + nt * 8 + 2 * cg + 1);
        }
#pragma unroll
        for (int mt = 0; mt < 2; mt++)
#pragma unroll
            for (int nt = 0; nt < 4; nt++) {
                acc[mt][nt][0] += bias[nt * 2];
                acc[mt][nt][1] += bias[nt * 2 + 1];
                acc[mt][nt][2] += bias[nt * 2];
                acc[mt][nt][3] += bias[nt * 2 + 1];
            }

#pragma unroll
        for (int mt = 0; mt < 2; mt++)
#pragma unroll
            for (int h = 0; h < 2; h++) {
                float m = -1e30f;
#pragma unroll
                for (int nt = 0; nt < 4; nt++) {
                    m = fmaxf(m, acc[mt][nt][2 * h]);
                    m = fmaxf(m, acc[mt][nt][2 * h + 1]);
                }
                m = fmaxf(m, __shfl_xor_sync(0xffffffffu, m, 1));
                m = fmaxf(m, __shfl_xor_sync(0xffffffffu, m, 2));
                float s = 0.f;
#pragma unroll
                for (int nt = 0; nt < 4; nt++) {
                    s += __expf(acc[mt][nt][2 * h] - m);
                    s += __expf(acc[mt][nt][2 * h + 1] - m);
                }
                s += __shfl_xor_sync(0xffffffffu, s, 1);
                s += __shfl_xor_sync(0xffffffffu, s, 2);
                if (cg == 0) {
                    int r = m_base + mt * 16 + h * 8 + q;
                    sm[SM_PM + wn * 64 + r] = m;
                    sm[SM_PS + wn * 64 + r] = s;
                }
            }

        // store raw logits (fixed up at the end)
#pragma unroll
        for (int mt = 0; mt < 2; mt++)
#pragma unroll
            for (int h = 0; h < 2; h++) {
                float* rp = rowp[mt][h] + n0 + n_base;
#pragma unroll
                for (int nt = 0; nt < 4; nt++) {
                    rp[nt * 8 + 2 * cg]     = acc[mt][nt][2 * h];
                    rp[nt * 8 + 2 * cg + 1] = acc[mt][nt][2 * h + 1];
                }
            }

        __syncthreads();
        if (tid < 64) {
            float m = sm[SM_M + tid], s = sm[SM_S + tid];
#pragma unroll
            for (int w = 0; w < 4; w++) {
                float mc = sm[SM_PM + w * 64 + tid];
                float sc = sm[SM_PS + w * 64 + tid];
                float mn = fmaxf(m, mc);
                s = s * __expf(m - mn) + sc * __expf(mc - mn);
                m = mn;
            }
            sm[SM_M + tid] = m;
            sm[SM_S + tid] = s;
        }
        __syncthreads();
    }

    // ---- column 1024 (stride-4 j access: conflict-free LDS) + LSE
    {
        int r = tid >> 2, part = tid & 3;
        const float* ar = sm + r * AS_STR;
        const float* wr = sm + SM_WL;
        float d = 0.f;
#pragma unroll 8
        for (int j = 0; j < 128; j++) {
            int jj = part + 4 * j;
            d += ar[jj] * wr[jj];
        }
        d += __shfl_xor_sync(0xffffffffu, d, 1);
        d += __shfl_xor_sync(0xffffffffu, d, 2);
        if (part == 0) {
            float v = d + __ldg(b_out + 1024);
            int t = t0 + (r >> 3), u = u0 + (r & 7);
            out[(size_t)((b * T_ + t) * U_ + u) * NC_ + 1024] = v;
            float m = sm[SM_M + r], s = sm[SM_S + r];
            float mn = fmaxf(m, v);
            s = s * __expf(m - mn) + __expf(v - mn);
            sm[SM_LSE + r] = mn + logf(s);
        }
    }
    __syncthreads();

    // ---- fixup: subtract LSE (L2-hot re-read of own rows)
    for (int r = 0; r < 64; r++) {
        float l = sm[SM_LSE + r];
        int t = t0 + (r >> 3), u = u0 + (r & 7);
        float* p = out + (size_t)((b * T_ + t) * U_ + u) * NC_;
        for (int c = tid; c < NC_; c += 256) p[c] -= l;
    }
}

// ---------------------------------------------------------------------------
// launcher
// ---------------------------------------------------------------------------
extern "C" void kernel_launch(void* const* d_in, const int* in_sizes, int n_in,
                              void* d_out, int out_size) {
    const float* enc    = (const float*)d_in[0];
    const float* dec    = (const float*)d_in[1];
    const float* W_enc  = (const float*)d_in[2];
    const float* b_enc  = (const float*)d_in[3];
    const float* W_pred = (const float*)d_in[4];
    const float* b_pred = (const float*)d_in[5];
    const float* W_out  = (const float*)d_in[6];
    const float* b_out  = (const float*)d_in[7];
    float* out = (float*)d_out;

    void *pe = nullptr, *pp = nullptr;
    cudaGetSymbolAddress(&pe, g_e);
    cudaGetSymbolAddress(&pp, g_p);

    static int smem_set = 0;
    cudaFuncSetAttribute(joint_kernel, cudaFuncAttributeMaxDynamicSharedMemorySize,
                         SM_TOT * 4);
    (void)smem_set;

    pack_kernel<<<2048, 256>>>(W_out);
    proj_kernel<<<dim3(8, 16), 256>>>(enc, W_enc, b_enc, (float*)pe, T_, EH_);
    proj_kernel<<<dim3(8, 8), 256>>>(dec, W_pred, b_pred, (float*)pp, U_, PH_);

    dim3 grid(U_ / 8, T_ / 8, B_);   // (16, 32, 4) = 2048 blocks
    joint_kernel<<<grid, 256, SM_TOT * 4>>>(b_out, out);
}

// round 5
// speedup vs baseline: 1.1165x; 1.1165x over previous
#include <cuda_runtime.h>
#include <cstdint>

#define B_  4
#define T_  256
#define U_  128
#define EH_ 512
#define PH_ 320
#define JH_ 512
#define NC_ 1025

// ---------------------------------------------------------------------------
// scratch (no cudaMalloc allowed)
// ---------------------------------------------------------------------------
__device__ float g_e[B_ * T_ * JH_];     // [b*T+t][512]  e + b_enc
__device__ float g_p[B_ * U_ * JH_];     // [b*U+u][512]  p + b_pred
__device__ float g_wp[JH_ * 1024];       // W_out cols 0..1023, fragment-packed
__device__ float g_wl[JH_];              // W_out col 1024

// ---------------------------------------------------------------------------
// helpers
// ---------------------------------------------------------------------------
__device__ __forceinline__ void mma_tf32(float* c, const float4& a, float bx, float by) {
    const unsigned* au = reinterpret_cast<const unsigned*>(&a);
    unsigned b0 = __float_as_uint(bx), b1 = __float_as_uint(by);
    asm volatile(
        "mma.sync.aligned.m16n8k8.row.col.f32.tf32.tf32.f32 "
        "{%0,%1,%2,%3},{%4,%5,%6,%7},{%8,%9},{%0,%1,%2,%3};\n"
        : "+f"(c[0]), "+f"(c[1]), "+f"(c[2]), "+f"(c[3])
        : "r"(au[0]), "r"(au[1]), "r"(au[2]), "r"(au[3]), "r"(b0), "r"(b1));
}

__device__ __forceinline__ void cpa16(uint32_t dst, const void* src) {
    asm volatile("cp.async.ca.shared.global [%0], [%1], 16;\n" :: "r"(dst), "l"(src) : "memory");
}
__device__ __forceinline__ void cpa_commit() {
    asm volatile("cp.async.commit_group;\n" ::: "memory");
}
__device__ __forceinline__ void cpa_wait2() {
    asm volatile("cp.async.wait_group 2;\n" ::: "memory");
}

// ---------------------------------------------------------------------------
// projection: O[row][j] = sum_h X[b][h][t] * W[h][j] + bias[j]
// ---------------------------------------------------------------------------
__global__ void __launch_bounds__(256)
proj_kernel(const float* __restrict__ X, const float* __restrict__ W,
            const float* __restrict__ bias, float* __restrict__ O,
            int L, int H) {
    __shared__ float Xs[16][64];
    __shared__ float Ws[16][64];
    int tid = threadIdx.x;
    int tc = tid & 15, tr = tid >> 4;
    int j0 = blockIdx.x * 64;
    int row0 = blockIdx.y * 64;
    int b = row0 / L;
    int t0 = row0 % L;

    float acc[4][4];
#pragma unroll
    for (int i = 0; i < 4; i++)
#pragma unroll
        for (int j = 0; j < 4; j++) acc[i][j] = 0.f;

    for (int k0 = 0; k0 < H; k0 += 16) {
#pragma unroll
        for (int i = 0; i < 4; i++) {
            int idx = tid + i * 256;
            int ky = idx >> 6, xx = idx & 63;
            Xs[ky][xx] = X[(size_t)(b * H + k0 + ky) * L + t0 + xx];
            Ws[ky][xx] = W[(size_t)(k0 + ky) * JH_ + j0 + xx];
        }
        __syncthreads();
#pragma unroll
        for (int k = 0; k < 16; k++) {
            float a[4], w[4];
#pragma unroll
            for (int i = 0; i < 4; i++) { a[i] = Xs[k][tr * 4 + i]; w[i] = Ws[k][tc * 4 + i]; }
#pragma unroll
            for (int i = 0; i < 4; i++)
#pragma unroll
                for (int j = 0; j < 4; j++) acc[i][j] += a[i] * w[j];
        }
        __syncthreads();
    }
#pragma unroll
    for (int i = 0; i < 4; i++)
#pragma unroll
        for (int j = 0; j < 4; j++) {
            int col = j0 + tc * 4 + j;
            O[(size_t)(row0 + tr * 4 + i) * JH_ + col] = acc[i][j] + bias[col];
        }
}

// ---------------------------------------------------------------------------
// pack W_out into mma-fragment order:
// float index d bits: reg4[0:2) lane[2:7) pair[7] wn[8:10) k8[10:12) kc[12:16) nc[16:19)
// value = W_out[j][c], j = kc*32 + k8*8 + (lane&3) + (reg4&1)*4
//                      c = nc*128 + wn*32 + (pair*2 + (reg4>>1))*8 + (lane>>2)
// ---------------------------------------------------------------------------
__global__ void pack_kernel(const float* __restrict__ W) {
    int d = blockIdx.x * 256 + threadIdx.x;
    if (d < JH_ * 1024) {
        int reg4 = d & 3;
        int lane = (d >> 2) & 31;
        int pair = (d >> 7) & 1;
        int wn   = (d >> 8) & 3;
        int k8   = (d >> 10) & 3;
        int kc   = (d >> 12) & 15;
        int nc   = d >> 16;
        int j = kc * 32 + k8 * 8 + (lane & 3) + (reg4 & 1) * 4;
        int c = nc * 128 + wn * 32 + (pair * 2 + (reg4 >> 1)) * 8 + (lane >> 2);
        g_wp[d] = W[(size_t)j * NC_ + c];
    }
    if (d < JH_) g_wl[d] = W[(size_t)d * NC_ + 1024];
}

// ---------------------------------------------------------------------------
// joint kernel
// ---------------------------------------------------------------------------
#define SM_BS  32768                     // A fragments: 32768 floats (128 KB)
#define SM_WL  (SM_BS + 4 * 4096)        // 49152: w_l copy (512)
#define SM_M   (SM_WL + 512)             // 49664
#define SM_S   (SM_M + 64)               // 49728
#define SM_PM  (SM_S + 64)               // 49792 [4][64]
#define SM_PS  (SM_PM + 256)             // 50048 [4][64]
#define SM_D   (SM_PS + 256)             // 50304 col-1024 dots
#define SM_LSE (SM_D + 64)               // 50368
#define SM_TOT (SM_LSE + 64)             // 50432 floats = 201728 B

__global__ void __launch_bounds__(256, 1)
joint_kernel(const float* __restrict__ b_out, float* __restrict__ out) {
    extern __shared__ float sm[];
    const int tid = threadIdx.x;
    const int lane = tid & 31, warp = tid >> 5;
    const int wm = warp & 1, wn = warp >> 1;      // 2 (m) x 4 (n)
    const int q = lane >> 2, cg = lane & 3;
    const int u0 = blockIdx.x * 8, t0 = blockIdx.y * 8, b = blockIdx.z;

    if (tid < 64) { sm[SM_M + tid] = -1e30f; sm[SM_S + tid] = 0.f; }
    for (int i = tid; i < 512; i += 256) sm[SM_WL + i] = g_wl[i];

    // preload B pipeline stages 0..2 (overlaps with the A build below)
    const uint32_t bs_base = (uint32_t)__cvta_generic_to_shared(sm + SM_BS);
#pragma unroll
    for (int s = 0; s < 3; s++) {
        uint32_t dst = bs_base + (uint32_t)s * 16384u + (uint32_t)tid * 16u;
        const float* src = g_wp + (size_t)s * 4096 + tid * 4;
#pragma unroll
        for (int i = 0; i < 4; i++) cpa16(dst + i * 4096u, src + i * 1024);
        cpa_commit();
    }
    __syncthreads();   // w_l / stats ready

    // ---- build A in fragment order + accumulate col-1024 dot
    // float index i: reg[0:2) flane[2:7) m16[7:9) k8[9:15)
    {
        const int reg   = tid & 3;
        const int q_b   = (tid >> 4) & 7;          // flane>>2
        const int m16b0 = (tid >> 7) & 1;
        const int rl    = q_b + 8 * (reg & 1);     // row within m16 tile
        const int jo    = ((tid >> 2) & 3) + 4 * (reg >> 1);
        const float* wl = sm + SM_WL;
        const float* pb  = g_p + ((size_t)(b * U_ + u0 + q_b) << 9);
        const float* eb0 = g_e + ((size_t)(b * T_ + t0 + 2 * m16b0 + (reg & 1)) << 9);
        const float* eb1 = eb0 + (4 << 9);
        float d2[2] = {0.f, 0.f};
#pragma unroll 4
        for (int k8g = 0; k8g < 64; k8g++) {
            int j = k8g * 8 + jo;
            float pv = pb[j];
            float wv = wl[j];
            // n even: m16 = m16b0
            {
                float v = fmaxf(eb0[j] + pv, 0.f);
                d2[0] += v * wv;
                unsigned uu; asm("cvt.rna.tf32.f32 %0,%1;" : "=r"(uu) : "f"(v));
                sm[(k8g * 2) * 256 + tid] = __uint_as_float(uu);
            }
            // n odd: m16 = m16b0 + 2
            {
                float v = fmaxf(eb1[j] + pv, 0.f);
                d2[1] += v * wv;
                unsigned uu; asm("cvt.rna.tf32.f32 %0,%1;" : "=r"(uu) : "f"(v));
                sm[(k8g * 2 + 1) * 256 + tid] = __uint_as_float(uu);
            }
        }
#pragma unroll
        for (int h = 0; h < 2; h++) {
            d2[h] += __shfl_xor_sync(0xffffffffu, d2[h], 2);
            d2[h] += __shfl_xor_sync(0xffffffffu, d2[h], 4);
            d2[h] += __shfl_xor_sync(0xffffffffu, d2[h], 8);
        }
        if ((lane & 14) == 0) {
            int r0 = m16b0 * 16 + rl;
            sm[SM_D + r0] = d2[0];
            sm[SM_D + r0 + 32] = d2[1];
        }
    }
    __syncthreads();

    // per-thread output row pointers: rows r = wm*32 + mt*16 + h*8 + q
    float* rowp[2][2];
#pragma unroll
    for (int mt = 0; mt < 2; mt++)
#pragma unroll
        for (int h = 0; h < 2; h++) {
            int r = wm * 32 + mt * 16 + h * 8 + q;
            int t = t0 + (r >> 3), u = u0 + (r & 7);
            rowp[mt][h] = out + (size_t)((b * T_ + t) * U_ + u) * NC_;
        }

    const float4* Af = (const float4*)sm + (wm * 2) * 32 + lane;       // + k8tot*128 (+32 for mt=1)
    const float4* Bbase = (const float4*)(sm + SM_BS) + wn * 64 + lane; // + stage*1024 + k8*256 (+32)

    for (int nc = 0; nc < 8; nc++) {
        float acc[2][4][4];
#pragma unroll
        for (int mt = 0; mt < 2; mt++)
#pragma unroll
            for (int nt = 0; nt < 4; nt++)
#pragma unroll
                for (int i = 0; i < 4; i++) acc[mt][nt][i] = 0.f;

        for (int kc = 0; kc < 16; kc++) {
            const int g = nc * 16 + kc;
            cpa_wait2();
            __syncthreads();
            // prefetch stage g+3
            {
                int gp = g + 3;
                if (gp < 128) {
                    uint32_t dst = bs_base + (uint32_t)(gp & 3) * 16384u + (uint32_t)tid * 16u;
                    const float* src = g_wp + (size_t)gp * 4096 + tid * 4;
#pragma unroll
                    for (int i = 0; i < 4; i++) cpa16(dst + i * 4096u, src + i * 1024);
                }
                cpa_commit();
            }
            const float4* As = Af + (size_t)(kc * 4) * 128;
            const float4* Bs = Bbase + (size_t)(g & 3) * 1024;
#pragma unroll
            for (int k8 = 0; k8 < 4; k8++) {
                float4 a0 = As[k8 * 128];
                float4 a1 = As[k8 * 128 + 32];
                float4 bb0 = Bs[k8 * 256];
                float4 bb1 = Bs[k8 * 256 + 32];
                mma_tf32(acc[0][0], a0, bb0.x, bb0.y);
                mma_tf32(acc[0][1], a0, bb0.z, bb0.w);
                mma_tf32(acc[0][2], a0, bb1.x, bb1.y);
                mma_tf32(acc[0][3], a0, bb1.z, bb1.w);
                mma_tf32(acc[1][0], a1, bb0.x, bb0.y);
                mma_tf32(acc[1][1], a1, bb0.z, bb0.w);
                mma_tf32(acc[1][2], a1, bb1.x, bb1.y);
                mma_tf32(acc[1][3], a1, bb1.z, bb1.w);
            }
        }

        // ---- epilogue: bias, online softmax partials, store raw logits
        const int n0 = nc * 128;
        float bias[8];
#pragma unroll
        for (int nt = 0; nt < 4; nt++) {
            bias[nt * 2]     = __ldg(b_out + n0 + wn * 32 + nt * 8 + 2 * cg);
            bias[nt * 2 + 1] = __ldg(b_out + n0 + wn * 32 + nt * 8 + 2 * cg + 1);
        }
#pragma unroll
        for (int mt = 0; mt < 2; mt++)
#pragma unroll
            for (int nt = 0; nt < 4; nt++) {
                acc[mt][nt][0] += bias[nt * 2];
                acc[mt][nt][1] += bias[nt * 2 + 1];
                acc[mt][nt][2] += bias[nt * 2];
                acc[mt][nt][3] += bias[nt * 2 + 1];
            }

#pragma unroll
        for (int mt = 0; mt < 2; mt++)
#pragma unroll
            for (int h = 0; h < 2; h++) {
                float m = -1e30f;
#pragma unroll
                for (int nt = 0; nt < 4; nt++) {
                    m = fmaxf(m, acc[mt][nt][2 * h]);
                    m = fmaxf(m, acc[mt][nt][2 * h + 1]);
                }
                m = fmaxf(m, __shfl_xor_sync(0xffffffffu, m, 1));
                m = fmaxf(m, __shfl_xor_sync(0xffffffffu, m, 2));
                float s = 0.f;
#pragma unroll
                for (int nt = 0; nt < 4; nt++) {
                    s += __expf(acc[mt][nt][2 * h] - m);
                    s += __expf(acc[mt][nt][2 * h + 1] - m);
                }
                s += __shfl_xor_sync(0xffffffffu, s, 1);
                s += __shfl_xor_sync(0xffffffffu, s, 2);
                if (cg == 0) {
                    int r = wm * 32 + mt * 16 + h * 8 + q;
                    sm[SM_PM + wn * 64 + r] = m;
                    sm[SM_PS + wn * 64 + r] = s;
                }
            }

#pragma unroll
        for (int mt = 0; mt < 2; mt++)
#pragma unroll
            for (int h = 0; h < 2; h++) {
                float* rp = rowp[mt][h] + n0 + wn * 32;
#pragma unroll
                for (int nt = 0; nt < 4; nt++) {
                    rp[nt * 8 + 2 * cg]     = acc[mt][nt][2 * h];
                    rp[nt * 8 + 2 * cg + 1] = acc[mt][nt][2 * h + 1];
                }
            }

        __syncthreads();
        if (tid < 64) {
            float m = sm[SM_M + tid], s = sm[SM_S + tid];
#pragma unroll
            for (int w = 0; w < 4; w++) {
                float mc = sm[SM_PM + w * 64 + tid];
                float sc = sm[SM_PS + w * 64 + tid];
                float mn = fmaxf(m, mc);
                s = s * __expf(m - mn) + sc * __expf(mc - mn);
                m = mn;
            }
            sm[SM_M + tid] = m;
            sm[SM_S + tid] = s;
        }
        __syncthreads();
    }

    // ---- col 1024 + final LSE
    if (tid < 64) {
        int r = tid;
        float v = sm[SM_D + r] + __ldg(b_out + 1024);
        float m = sm[SM_M + r], s = sm[SM_S + r];
        float mn = fmaxf(m, v);
        s = s * __expf(m - mn) + __expf(v - mn);
        float lse = mn + logf(s);
        sm[SM_LSE + r] = lse;
        int t = t0 + (r >> 3), u = u0 + (r & 7);
        out[(size_t)((b * T_ + t) * U_ + u) * NC_ + 1024] = v - lse;
    }
    __syncthreads();

    // ---- fixup: subtract LSE from cols 0..1023 (L2-hot)
    {
        const size_t base = (size_t)((b * T_ + t0) * U_ + u0) * NC_;
#pragma unroll 4
        for (int idx = tid; idx < 64 * 1024; idx += 256) {
            int r = idx >> 10, c = idx & 1023;
            float l = sm[SM_LSE + r];
            size_t off = base + (size_t)(r >> 3) * (U_ * NC_) + (size_t)(r & 7) * NC_ + c;
            out[off] -= l;
        }
    }
}

// ---------------------------------------------------------------------------
// launcher
// ---------------------------------------------------------------------------
extern "C" void kernel_launch(void* const* d_in, const int* in_sizes, int n_in,
                              void* d_out, int out_size) {
    const float* enc    = (const float*)d_in[0];
    const float* dec    = (const float*)d_in[1];
    const float* W_enc  = (const float*)d_in[2];
    const float* b_enc  = (const float*)d_in[3];
    const float* W_pred = (const float*)d_in[4];
    const float* b_pred = (const float*)d_in[5];
    const float* W_out  = (const float*)d_in[6];
    const float* b_out  = (const float*)d_in[7];
    float* out = (float*)d_out;

    void *pe = nullptr, *pp = nullptr;
    cudaGetSymbolAddress(&pe, g_e);
    cudaGetSymbolAddress(&pp, g_p);

    cudaFuncSetAttribute(joint_kernel, cudaFuncAttributeMaxDynamicSharedMemorySize,
                         SM_TOT * 4);

    pack_kernel<<<2048, 256>>>(W_out);
    proj_kernel<<<dim3(8, 16), 256>>>(enc, W_enc, b_enc, (float*)pe, T_, EH_);
    proj_kernel<<<dim3(8, 8), 256>>>(dec, W_pred, b_pred, (float*)pp, U_, PH_);

    dim3 grid(U_ / 8, T_ / 8, B_);   // (16, 32, 4) = 2048 blocks
    joint_kernel<<<grid, 256, SM_TOT * 4>>>(b_out, out);
}

// round 6
// speedup vs baseline: 1.1710x; 1.0488x over previous
#include <cuda_runtime.h>
#include <cstdint>

#define B_  4
#define T_  256
#define U_  128
#define EH_ 512
#define PH_ 320
#define JH_ 512
#define NC_ 1025

// ---------------------------------------------------------------------------
// scratch (no cudaMalloc allowed)
// ---------------------------------------------------------------------------
__device__ float g_e[B_ * T_ * JH_];     // [b*T+t][512]  e + b_enc
__device__ float g_p[B_ * U_ * JH_];     // [b*U+u][512]  p + b_pred
__device__ float g_wp[JH_ * 1024];       // W_out cols 0..1023, fragment-packed
__device__ float g_wl[JH_];              // W_out col 1024

// ---------------------------------------------------------------------------
// helpers
// ---------------------------------------------------------------------------
__device__ __forceinline__ void mma_tf32(float* c, const float4& a, float bx, float by) {
    const unsigned* au = reinterpret_cast<const unsigned*>(&a);
    unsigned b0 = __float_as_uint(bx), b1 = __float_as_uint(by);
    asm volatile(
        "mma.sync.aligned.m16n8k8.row.col.f32.tf32.tf32.f32 "
        "{%0,%1,%2,%3},{%4,%5,%6,%7},{%8,%9},{%0,%1,%2,%3};\n"
        : "+f"(c[0]), "+f"(c[1]), "+f"(c[2]), "+f"(c[3])
        : "r"(au[0]), "r"(au[1]), "r"(au[2]), "r"(au[3]), "r"(b0), "r"(b1));
}

__device__ __forceinline__ void mbar_init(uint32_t mbar, uint32_t count) {
    asm volatile("mbarrier.init.shared.b64 [%0], %1;\n" :: "r"(mbar), "r"(count) : "memory");
}
__device__ __forceinline__ void mbar_expect_tx(uint32_t mbar, uint32_t bytes) {
    asm volatile("mbarrier.arrive.expect_tx.shared.b64 _, [%0], %1;\n"
                 :: "r"(mbar), "r"(bytes) : "memory");
}
__device__ __forceinline__ void bulk_g2s(uint32_t dst, const void* src, uint32_t bytes,
                                         uint32_t mbar) {
    asm volatile(
        "cp.async.bulk.shared::cluster.global.mbarrier::complete_tx::bytes "
        "[%0], [%1], %2, [%3];\n"
        :: "r"(dst), "l"(src), "r"(bytes), "r"(mbar) : "memory");
}
__device__ __forceinline__ void mbar_wait(uint32_t mbar, uint32_t parity) {
    uint32_t done;
    asm volatile(
        "{\n\t.reg .pred p;\n\t"
        "mbarrier.try_wait.parity.acquire.cta.shared::cta.b64 p, [%1], %2;\n\t"
        "selp.b32 %0, 1, 0, p;\n\t}"
        : "=r"(done) : "r"(mbar), "r"(parity) : "memory");
    if (!done) {
        asm volatile(
            "{\n\t.reg .pred P1;\n\t"
            "W_%=:\n\t"
            "mbarrier.try_wait.parity.acquire.cta.shared::cta.b64 P1, [%0], %1, 0x989680;\n\t"
            "@P1 bra.uni D_%=;\n\t"
            "bra.uni W_%=;\n\t"
            "D_%=:\n\t}"
            :: "r"(mbar), "r"(parity) : "memory");
    }
}

// ---------------------------------------------------------------------------
// projection: O[row][j] = sum_h X[b][h][t] * W[h][j] + bias[j]
// ---------------------------------------------------------------------------
__global__ void __launch_bounds__(256)
proj_kernel(const float* __restrict__ X, const float* __restrict__ W,
            const float* __restrict__ bias, float* __restrict__ O,
            int L, int H) {
    __shared__ float Xs[16][64];
    __shared__ float Ws[16][64];
    int tid = threadIdx.x;
    int tc = tid & 15, tr = tid >> 4;
    int j0 = blockIdx.x * 64;
    int row0 = blockIdx.y * 64;
    int b = row0 / L;
    int t0 = row0 % L;

    float acc[4][4];
#pragma unroll
    for (int i = 0; i < 4; i++)
#pragma unroll
        for (int j = 0; j < 4; j++) acc[i][j] = 0.f;

    for (int k0 = 0; k0 < H; k0 += 16) {
#pragma unroll
        for (int i = 0; i < 4; i++) {
            int idx = tid + i * 256;
            int ky = idx >> 6, xx = idx & 63;
            Xs[ky][xx] = X[(size_t)(b * H + k0 + ky) * L + t0 + xx];
            Ws[ky][xx] = W[(size_t)(k0 + ky) * JH_ + j0 + xx];
        }
        __syncthreads();
#pragma unroll
        for (int k = 0; k < 16; k++) {
            float a[4], w[4];
#pragma unroll
            for (int i = 0; i < 4; i++) { a[i] = Xs[k][tr * 4 + i]; w[i] = Ws[k][tc * 4 + i]; }
#pragma unroll
            for (int i = 0; i < 4; i++)
#pragma unroll
                for (int j = 0; j < 4; j++) acc[i][j] += a[i] * w[j];
        }
        __syncthreads();
    }
#pragma unroll
    for (int i = 0; i < 4; i++)
#pragma unroll
        for (int j = 0; j < 4; j++) {
            int col = j0 + tc * 4 + j;
            O[(size_t)(row0 + tr * 4 + i) * JH_ + col] = acc[i][j] + bias[col];
        }
}

// ---------------------------------------------------------------------------
// pack W_out into mma-fragment order (see bit layout in comments)
// ---------------------------------------------------------------------------
__global__ void pack_kernel(const float* __restrict__ W) {
    int d = blockIdx.x * 256 + threadIdx.x;
    if (d < JH_ * 1024) {
        int reg4 = d & 3;
        int lane = (d >> 2) & 31;
        int pair = (d >> 7) & 1;
        int wn   = (d >> 8) & 3;
        int k8   = (d >> 10) & 3;
        int kc   = (d >> 12) & 15;
        int nc   = d >> 16;
        int j = kc * 32 + k8 * 8 + (lane & 3) + (reg4 & 1) * 4;
        int c = nc * 128 + wn * 32 + (pair * 2 + (reg4 >> 1)) * 8 + (lane >> 2);
        g_wp[d] = W[(size_t)j * NC_ + c];
    }
    if (d < JH_) g_wl[d] = W[(size_t)d * NC_ + 1024];
}

// ---------------------------------------------------------------------------
// joint kernel
// ---------------------------------------------------------------------------
#define SM_BS  32768                     // A fragments: 32768 floats (128 KB)
#define SM_WL  (SM_BS + 4 * 4096)        // 49152: w_l copy (512)
#define SM_M   (SM_WL + 512)             // 49664
#define SM_S   (SM_M + 64)               // 49728
#define SM_PM  (SM_S + 64)               // 49792 [4][64]
#define SM_PS  (SM_PM + 256)             // 50048 [4][64]
#define SM_D   (SM_PS + 256)             // 50304 col-1024 dots
#define SM_LSE (SM_D + 64)               // 50368
#define SM_MBAR (SM_LSE + 64)            // 50432 (8B aligned): 4 mbarriers
#define SM_TOT (SM_MBAR + 16)            // 50448 floats = 201792 B

#define STAGE_BYTES 16384u

__global__ void __launch_bounds__(256, 1)
joint_kernel(const float* __restrict__ b_out, float* __restrict__ out) {
    extern __shared__ float sm[];
    const int tid = threadIdx.x;
    const int lane = tid & 31, warp = tid >> 5;
    const int wm = warp & 1, wn = warp >> 1;      // 2 (m) x 4 (n)
    const int q = lane >> 2, cg = lane & 3;
    const int u0 = blockIdx.x * 8, t0 = blockIdx.y * 8, b = blockIdx.z;

    const uint32_t bs_base = (uint32_t)__cvta_generic_to_shared(sm + SM_BS);
    const uint32_t mbar0 = (uint32_t)__cvta_generic_to_shared(sm + SM_MBAR);

    if (tid < 64) { sm[SM_M + tid] = -1e30f; sm[SM_S + tid] = 0.f; }
    for (int i = tid; i < 512; i += 256) sm[SM_WL + i] = g_wl[i];

    if (tid == 0) {
#pragma unroll
        for (int s = 0; s < 4; s++) mbar_init(mbar0 + 8u * s, 1);
    }
    __syncthreads();
    // preload B stages 0..2 (overlap with A build)
    if (tid == 0) {
#pragma unroll
        for (int s = 0; s < 3; s++) {
            mbar_expect_tx(mbar0 + 8u * s, STAGE_BYTES);
            bulk_g2s(bs_base + (uint32_t)s * STAGE_BYTES, g_wp + (size_t)s * 4096,
                     STAGE_BYTES, mbar0 + 8u * s);
        }
    }

    // ---- build A in fragment order + accumulate col-1024 dot
    {
        const int reg   = tid & 3;
        const int q_b   = (tid >> 4) & 7;
        const int m16b0 = (tid >> 7) & 1;
        const int rl    = q_b + 8 * (reg & 1);
        const int jo    = ((tid >> 2) & 3) + 4 * (reg >> 1);
        const float* wl = sm + SM_WL;
        const float* pb  = g_p + ((size_t)(b * U_ + u0 + q_b) << 9);
        const float* eb0 = g_e + ((size_t)(b * T_ + t0 + 2 * m16b0 + (reg & 1)) << 9);
        const float* eb1 = eb0 + (4 << 9);
        float d2[2] = {0.f, 0.f};
#pragma unroll 4
        for (int k8g = 0; k8g < 64; k8g++) {
            int j = k8g * 8 + jo;
            float pv = pb[j];
            float wv = wl[j];
            {
                float v = fmaxf(eb0[j] + pv, 0.f);
                d2[0] += v * wv;
                unsigned uu; asm("cvt.rna.tf32.f32 %0,%1;" : "=r"(uu) : "f"(v));
                sm[(k8g * 2) * 256 + tid] = __uint_as_float(uu);
            }
            {
                float v = fmaxf(eb1[j] + pv, 0.f);
                d2[1] += v * wv;
                unsigned uu; asm("cvt.rna.tf32.f32 %0,%1;" : "=r"(uu) : "f"(v));
                sm[(k8g * 2 + 1) * 256 + tid] = __uint_as_float(uu);
            }
        }
#pragma unroll
        for (int h = 0; h < 2; h++) {
            d2[h] += __shfl_xor_sync(0xffffffffu, d2[h], 2);
            d2[h] += __shfl_xor_sync(0xffffffffu, d2[h], 4);
            d2[h] += __shfl_xor_sync(0xffffffffu, d2[h], 8);
        }
        if ((lane & 14) == 0) {
            int r0 = m16b0 * 16 + rl;
            sm[SM_D + r0] = d2[0];
            sm[SM_D + r0 + 32] = d2[1];
        }
    }
    __syncthreads();

    // per-thread output row pointers: rows r = wm*32 + mt*16 + h*8 + q
    float* rowp[2][2];
#pragma unroll
    for (int mt = 0; mt < 2; mt++)
#pragma unroll
        for (int h = 0; h < 2; h++) {
            int r = wm * 32 + mt * 16 + h * 8 + q;
            int t = t0 + (r >> 3), u = u0 + (r & 7);
            rowp[mt][h] = out + (size_t)((b * T_ + t) * U_ + u) * NC_;
        }

    const float4* Af = (const float4*)sm + (wm * 2) * 32 + lane;        // + kc*512 + k8*128 (+32 mt=1)
    const float4* Bbase = (const float4*)(sm + SM_BS) + wn * 64 + lane; // + stage*1024 + k8*256 (+32)

    for (int nc = 0; nc < 8; nc++) {
        float acc[2][4][4];
#pragma unroll
        for (int mt = 0; mt < 2; mt++)
#pragma unroll
            for (int nt = 0; nt < 4; nt++)
#pragma unroll
                for (int i = 0; i < 4; i++) acc[mt][nt][i] = 0.f;

        for (int kc = 0; kc < 16; kc++) {
            const int g = nc * 16 + kc;
            mbar_wait(mbar0 + 8u * (g & 3), (g >> 2) & 1);
            __syncthreads();   // buffer (g-1)&3 now free for reuse
            if (tid == 0) {
                int gp = g + 3;
                if (gp < 128) {
                    uint32_t mb = mbar0 + 8u * (gp & 3);
                    mbar_expect_tx(mb, STAGE_BYTES);
                    bulk_g2s(bs_base + (uint32_t)(gp & 3) * STAGE_BYTES,
                             g_wp + (size_t)gp * 4096, STAGE_BYTES, mb);
                }
            }
            const float4* As = Af + (size_t)(kc * 4) * 128;
            const float4* Bs = Bbase + (size_t)(g & 3) * 1024;
#pragma unroll
            for (int k8 = 0; k8 < 4; k8++) {
                float4 a0 = As[k8 * 128];
                float4 a1 = As[k8 * 128 + 32];
                float4 bb0 = Bs[k8 * 256];
                float4 bb1 = Bs[k8 * 256 + 32];
                mma_tf32(acc[0][0], a0, bb0.x, bb0.y);
                mma_tf32(acc[0][1], a0, bb0.z, bb0.w);
                mma_tf32(acc[0][2], a0, bb1.x, bb1.y);
                mma_tf32(acc[0][3], a0, bb1.z, bb1.w);
                mma_tf32(acc[1][0], a1, bb0.x, bb0.y);
                mma_tf32(acc[1][1], a1, bb0.z, bb0.w);
                mma_tf32(acc[1][2], a1, bb1.x, bb1.y);
                mma_tf32(acc[1][3], a1, bb1.z, bb1.w);
            }
        }

        // ---- epilogue: bias, online softmax partials, store raw logits
        const int n0 = nc * 128;
        float bias[8];
#pragma unroll
        for (int nt = 0; nt < 4; nt++) {
            bias[nt * 2]     = __ldg(b_out + n0 + wn * 32 + nt * 8 + 2 * cg);
            bias[nt * 2 + 1] = __ldg(b_out + n0 + wn * 32 + nt * 8 + 2 * cg + 1);
        }
#pragma unroll
        for (int mt = 0; mt < 2; mt++)
#pragma unroll
            for (int nt = 0; nt < 4; nt++) {
                acc[mt][nt][0] += bias[nt * 2];
                acc[mt][nt][1] += bias[nt * 2 + 1];
                acc[mt][nt][2] += bias[nt * 2];
                acc[mt][nt][3] += bias[nt * 2 + 1];
            }

#pragma unroll
        for (int mt = 0; mt < 2; mt++)
#pragma unroll
            for (int h = 0; h < 2; h++) {
                float m = -1e30f;
#pragma unroll
                for (int nt = 0; nt < 4; nt++) {
                    m = fmaxf(m, acc[mt][nt][2 * h]);
                    m = fmaxf(m, acc[mt][nt][2 * h + 1]);
                }
                m = fmaxf(m, __shfl_xor_sync(0xffffffffu, m, 1));
                m = fmaxf(m, __shfl_xor_sync(0xffffffffu, m, 2));
                float s = 0.f;
#pragma unroll
                for (int nt = 0; nt < 4; nt++) {
                    s += __expf(acc[mt][nt][2 * h] - m);
                    s += __expf(acc[mt][nt][2 * h + 1] - m);
                }
                s += __shfl_xor_sync(0xffffffffu, s, 1);
                s += __shfl_xor_sync(0xffffffffu, s, 2);
                if (cg == 0) {
                    int r = wm * 32 + mt * 16 + h * 8 + q;
                    sm[SM_PM + wn * 64 + r] = m;
                    sm[SM_PS + wn * 64 + r] = s;
                }
            }

#pragma unroll
        for (int mt = 0; mt < 2; mt++)
#pragma unroll
            for (int h = 0; h < 2; h++) {
                float* rp = rowp[mt][h] + n0 + wn * 32;
#pragma unroll
                for (int nt = 0; nt < 4; nt++) {
                    rp[nt * 8 + 2 * cg]     = acc[mt][nt][2 * h];
                    rp[nt * 8 + 2 * cg + 1] = acc[mt][nt][2 * h + 1];
                }
            }

        __syncthreads();
        if (tid < 64) {
            float m = sm[SM_M + tid], s = sm[SM_S + tid];
#pragma unroll
            for (int w = 0; w < 4; w++) {
                float mc = sm[SM_PM + w * 64 + tid];
                float sc = sm[SM_PS + w * 64 + tid];
                float mn = fmaxf(m, mc);
                s = s * __expf(m - mn) + sc * __expf(mc - mn);
                m = mn;
            }
            sm[SM_M + tid] = m;
            sm[SM_S + tid] = s;
        }
        __syncthreads();
    }

    // ---- col 1024 + final LSE
    if (tid < 64) {
        int r = tid;
        float v = sm[SM_D + r] + __ldg(b_out + 1024);
        float m = sm[SM_M + r], s = sm[SM_S + r];
        float mn = fmaxf(m, v);
        s = s * __expf(m - mn) + __expf(v - mn);
        float lse = mn + logf(s);
        sm[SM_LSE + r] = lse;
        int t = t0 + (r >> 3), u = u0 + (r & 7);
        out[(size_t)((b * T_ + t) * U_ + u) * NC_ + 1024] = v - lse;
    }
    __syncthreads();

    // ---- fixup: subtract LSE from cols 0..1023 (L2-hot)
    {
        const size_t base = (size_t)((b * T_ + t0) * U_ + u0) * NC_;
#pragma unroll 4
        for (int idx = tid; idx < 64 * 1024; idx += 256) {
            int r = idx >> 10, c = idx & 1023;
            float l = sm[SM_LSE + r];
            size_t off = base + (size_t)(r >> 3) * (U_ * NC_) + (size_t)(r & 7) * NC_ + c;
            out[off] -= l;
        }
    }
}

// ---------------------------------------------------------------------------
// launcher
// ---------------------------------------------------------------------------
extern "C" void kernel_launch(void* const* d_in, const int* in_sizes, int n_in,
                              void* d_out, int out_size) {
    const float* enc    = (const float*)d_in[0];
    const float* dec    = (const float*)d_in[1];
    const float* W_enc  = (const float*)d_in[2];
    const float* b_enc  = (const float*)d_in[3];
    const float* W_pred = (const float*)d_in[4];
    const float* b_pred = (const float*)d_in[5];
    const float* W_out  = (const float*)d_in[6];
    const float* b_out  = (const float*)d_in[7];
    float* out = (float*)d_out;

    void *pe = nullptr, *pp = nullptr;
    cudaGetSymbolAddress(&pe, g_e);
    cudaGetSymbolAddress(&pp, g_p);

    cudaFuncSetAttribute(joint_kernel, cudaFuncAttributeMaxDynamicSharedMemorySize,
                         SM_TOT * 4);

    pack_kernel<<<2048, 256>>>(W_out);
    proj_kernel<<<dim3(8, 16), 256>>>(enc, W_enc, b_enc, (float*)pe, T_, EH_);
    proj_kernel<<<dim3(8, 8), 256>>>(dec, W_pred, b_pred, (float*)pp, U_, PH_);

    dim3 grid(U_ / 8, T_ / 8, B_);   // (16, 32, 4) = 2048 blocks
    joint_kernel<<<grid, 256, SM_TOT * 4>>>(b_out, out);
}

// round 7
// speedup vs baseline: 1.2641x; 1.0795x over previous
#include <cuda_runtime.h>
#include <cstdint>

#define B_  4
#define T_  256
#define U_  128
#define EH_ 512
#define PH_ 320
#define JH_ 512
#define NC_ 1025

// ---------------------------------------------------------------------------
// scratch (no cudaMalloc allowed)
// ---------------------------------------------------------------------------
__device__ float g_e[B_ * T_ * JH_];     // [b*T+t][512]  e + b_enc
__device__ float g_p[B_ * U_ * JH_];     // [b*U+u][512]  p + b_pred
__device__ float g_wp[JH_ * 1024];       // W_out cols 0..1023, fragment-packed
__device__ float g_wl[JH_];              // W_out col 1024

// ---------------------------------------------------------------------------
// helpers
// ---------------------------------------------------------------------------
__device__ __forceinline__ void mma_tf32(float* c, const float4& a, float bx, float by) {
    const unsigned* au = reinterpret_cast<const unsigned*>(&a);
    unsigned b0 = __float_as_uint(bx), b1 = __float_as_uint(by);
    asm volatile(
        "mma.sync.aligned.m16n8k8.row.col.f32.tf32.tf32.f32 "
        "{%0,%1,%2,%3},{%4,%5,%6,%7},{%8,%9},{%0,%1,%2,%3};\n"
        : "+f"(c[0]), "+f"(c[1]), "+f"(c[2]), "+f"(c[3])
        : "r"(au[0]), "r"(au[1]), "r"(au[2]), "r"(au[3]), "r"(b0), "r"(b1));
}

__device__ __forceinline__ void mbar_init(uint32_t mbar, uint32_t count) {
    asm volatile("mbarrier.init.shared.b64 [%0], %1;\n" :: "r"(mbar), "r"(count) : "memory");
}
__device__ __forceinline__ void mbar_expect_tx(uint32_t mbar, uint32_t bytes) {
    asm volatile("mbarrier.arrive.expect_tx.shared.b64 _, [%0], %1;\n"
                 :: "r"(mbar), "r"(bytes) : "memory");
}
__device__ __forceinline__ void mbar_arrive(uint32_t mbar) {
    asm volatile("mbarrier.arrive.release.cta.shared::cta.b64 _, [%0];\n"
                 :: "r"(mbar) : "memory");
}
__device__ __forceinline__ void bulk_g2s(uint32_t dst, const void* src, uint32_t bytes,
                                         uint32_t mbar) {
    asm volatile(
        "cp.async.bulk.shared::cluster.global.mbarrier::complete_tx::bytes "
        "[%0], [%1], %2, [%3];\n"
        :: "r"(dst), "l"(src), "r"(bytes), "r"(mbar) : "memory");
}
__device__ __forceinline__ void mbar_wait(uint32_t mbar, uint32_t parity) {
    uint32_t done;
    asm volatile(
        "{\n\t.reg .pred p;\n\t"
        "mbarrier.try_wait.parity.acquire.cta.shared::cta.b64 p, [%1], %2;\n\t"
        "selp.b32 %0, 1, 0, p;\n\t}"
        : "=r"(done) : "r"(mbar), "r"(parity) : "memory");
    if (!done) {
        asm volatile(
            "{\n\t.reg .pred P1;\n\t"
            "W_%=:\n\t"
            "mbarrier.try_wait.parity.acquire.cta.shared::cta.b64 P1, [%0], %1, 0x989680;\n\t"
            "@P1 bra.uni D_%=;\n\t"
            "bra.uni W_%=;\n\t"
            "D_%=:\n\t}"
            :: "r"(mbar), "r"(parity) : "memory");
    }
}

// ---------------------------------------------------------------------------
// projection: O[row][j] = sum_h X[b][h][t] * W[h][j] + bias[j]
// ---------------------------------------------------------------------------
__global__ void __launch_bounds__(256)
proj_kernel(const float* __restrict__ X, const float* __restrict__ W,
            const float* __restrict__ bias, float* __restrict__ O,
            int L, int H) {
    __shared__ float Xs[16][64];
    __shared__ float Ws[16][64];
    int tid = threadIdx.x;
    int tc = tid & 15, tr = tid >> 4;
    int j0 = blockIdx.x * 64;
    int row0 = blockIdx.y * 64;
    int b = row0 / L;
    int t0 = row0 % L;

    float acc[4][4];
#pragma unroll
    for (int i = 0; i < 4; i++)
#pragma unroll
        for (int j = 0; j < 4; j++) acc[i][j] = 0.f;

    for (int k0 = 0; k0 < H; k0 += 16) {
#pragma unroll
        for (int i = 0; i < 4; i++) {
            int idx = tid + i * 256;
            int ky = idx >> 6, xx = idx & 63;
            Xs[ky][xx] = X[(size_t)(b * H + k0 + ky) * L + t0 + xx];
            Ws[ky][xx] = W[(size_t)(k0 + ky) * JH_ + j0 + xx];
        }
        __syncthreads();
#pragma unroll
        for (int k = 0; k < 16; k++) {
            float a[4], w[4];
#pragma unroll
            for (int i = 0; i < 4; i++) { a[i] = Xs[k][tr * 4 + i]; w[i] = Ws[k][tc * 4 + i]; }
#pragma unroll
            for (int i = 0; i < 4; i++)
#pragma unroll
                for (int j = 0; j < 4; j++) acc[i][j] += a[i] * w[j];
        }
        __syncthreads();
    }
#pragma unroll
    for (int i = 0; i < 4; i++)
#pragma unroll
        for (int j = 0; j < 4; j++) {
            int col = j0 + tc * 4 + j;
            O[(size_t)(row0 + tr * 4 + i) * JH_ + col] = acc[i][j] + bias[col];
        }
}

// ---------------------------------------------------------------------------
// pack W_out into mma-fragment order
// ---------------------------------------------------------------------------
__global__ void pack_kernel(const float* __restrict__ W) {
    int d = blockIdx.x * 256 + threadIdx.x;
    if (d < JH_ * 1024) {
        int reg4 = d & 3;
        int lane = (d >> 2) & 31;
        int pair = (d >> 7) & 1;
        int wn   = (d >> 8) & 3;
        int k8   = (d >> 10) & 3;
        int kc   = (d >> 12) & 15;
        int nc   = d >> 16;
        int j = kc * 32 + k8 * 8 + (lane & 3) + (reg4 & 1) * 4;
        int c = nc * 128 + wn * 32 + (pair * 2 + (reg4 >> 1)) * 8 + (lane >> 2);
        g_wp[d] = W[(size_t)j * NC_ + c];
    }
    if (d < JH_) g_wl[d] = W[(size_t)d * NC_ + 1024];
}

// ---------------------------------------------------------------------------
// joint kernel
// ---------------------------------------------------------------------------
#define SM_BS  32768                     // A fragments: 32768 floats (128 KB)
#define SM_WL  (SM_BS + 4 * 4096)        // 49152: w_l copy (512)
#define SM_M   (SM_WL + 512)             // 49664
#define SM_S   (SM_M + 64)               // 49728
#define SM_PM  (SM_S + 64)               // 49792 [4][64]
#define SM_PS  (SM_PM + 256)             // 50048 [4][64]
#define SM_D   (SM_PS + 256)             // 50304 col-1024 dots
#define SM_LSE (SM_D + 64)               // 50368
#define SM_MBAR (SM_LSE + 64)            // 50432: 4 full + 4 empty mbarriers (64B)
#define SM_TOT (SM_MBAR + 16)            // 50448 floats = 201792 B

#define STAGE_BYTES 16384u

__global__ void __launch_bounds__(256, 1)
joint_kernel(const float* __restrict__ b_out, float* __restrict__ out) {
    extern __shared__ float sm[];
    const int tid = threadIdx.x;
    const int lane = tid & 31, warp = tid >> 5;
    const int wm = warp & 1, wn = warp >> 1;      // 2 (m) x 4 (n)
    const int q = lane >> 2, cg = lane & 3;
    const int u0 = blockIdx.x * 8, t0 = blockIdx.y * 8, b = blockIdx.z;

    const uint32_t bs_base = (uint32_t)__cvta_generic_to_shared(sm + SM_BS);
    const uint32_t mb_full = (uint32_t)__cvta_generic_to_shared(sm + SM_MBAR);
    const uint32_t mb_emp  = mb_full + 32u;

    if (tid < 64) { sm[SM_M + tid] = -1e30f; sm[SM_S + tid] = 0.f; }
    for (int i = tid; i < 512; i += 256) sm[SM_WL + i] = g_wl[i];

    if (tid == 0) {
#pragma unroll
        for (int s = 0; s < 4; s++) {
            mbar_init(mb_full + 8u * s, 1);
            mbar_init(mb_emp + 8u * s, 8);     // one arrive per warp
        }
    }
    __syncthreads();
    // preload B stages 0..2 (overlap with A build)
    if (tid == 0) {
#pragma unroll
        for (int s = 0; s < 3; s++) {
            mbar_expect_tx(mb_full + 8u * s, STAGE_BYTES);
            bulk_g2s(bs_base + (uint32_t)s * STAGE_BYTES, g_wp + (size_t)s * 4096,
                     STAGE_BYTES, mb_full + 8u * s);
        }
    }

    // ---- build A in fragment order + accumulate col-1024 dot
    {
        const int reg   = tid & 3;
        const int q_b   = (tid >> 4) & 7;
        const int m16b0 = (tid >> 7) & 1;
        const int rl    = q_b + 8 * (reg & 1);
        const int jo    = ((tid >> 2) & 3) + 4 * (reg >> 1);
        const float* wl = sm + SM_WL;
        const float* pb  = g_p + ((size_t)(b * U_ + u0 + q_b) << 9);
        const float* eb0 = g_e + ((size_t)(b * T_ + t0 + 2 * m16b0 + (reg & 1)) << 9);
        const float* eb1 = eb0 + (4 << 9);
        float d2[2] = {0.f, 0.f};
#pragma unroll 4
        for (int k8g = 0; k8g < 64; k8g++) {
            int j = k8g * 8 + jo;
            float pv = pb[j];
            float wv = wl[j];
            {
                float v = fmaxf(eb0[j] + pv, 0.f);
                d2[0] += v * wv;
                unsigned uu; asm("cvt.rna.tf32.f32 %0,%1;" : "=r"(uu) : "f"(v));
                sm[(k8g * 2) * 256 + tid] = __uint_as_float(uu);
            }
            {
                float v = fmaxf(eb1[j] + pv, 0.f);
                d2[1] += v * wv;
                unsigned uu; asm("cvt.rna.tf32.f32 %0,%1;" : "=r"(uu) : "f"(v));
                sm[(k8g * 2 + 1) * 256 + tid] = __uint_as_float(uu);
            }
        }
#pragma unroll
        for (int h = 0; h < 2; h++) {
            d2[h] += __shfl_xor_sync(0xffffffffu, d2[h], 2);
            d2[h] += __shfl_xor_sync(0xffffffffu, d2[h], 4);
            d2[h] += __shfl_xor_sync(0xffffffffu, d2[h], 8);
        }
        if ((lane & 14) == 0) {
            int r0 = m16b0 * 16 + rl;
            sm[SM_D + r0] = d2[0];
            sm[SM_D + r0 + 32] = d2[1];
        }
    }
    __syncthreads();

    // per-thread output row pointers: rows r = wm*32 + mt*16 + h*8 + q
    float* rowp[2][2];
#pragma unroll
    for (int mt = 0; mt < 2; mt++)
#pragma unroll
        for (int h = 0; h < 2; h++) {
            int r = wm * 32 + mt * 16 + h * 8 + q;
            int t = t0 + (r >> 3), u = u0 + (r & 7);
            rowp[mt][h] = out + (size_t)((b * T_ + t) * U_ + u) * NC_;
        }

    const float4* Af = (const float4*)sm + (wm * 2) * 32 + lane;        // + kc*512 + k8*128 (+32 mt=1)
    const float4* Bbase = (const float4*)(sm + SM_BS) + wn * 64 + lane; // + stage*1024 + k8*256 (+32)

    for (int nc = 0; nc < 8; nc++) {
        float acc[2][4][4];
#pragma unroll
        for (int mt = 0; mt < 2; mt++)
#pragma unroll
            for (int nt = 0; nt < 4; nt++)
#pragma unroll
                for (int i = 0; i < 4; i++) acc[mt][nt][i] = 0.f;

        for (int kc = 0; kc < 16; kc++) {
            const int g = nc * 16 + kc;
            // per-warp wait: stage g data ready
            mbar_wait(mb_full + 8u * (g & 3), (g >> 2) & 1);

            const float4* As = Af + (size_t)(kc * 4) * 128;
            const float4* Bs = Bbase + (size_t)(g & 3) * 1024;
#pragma unroll
            for (int k8 = 0; k8 < 4; k8++) {
                float4 a0 = As[k8 * 128];
                float4 a1 = As[k8 * 128 + 32];
                float4 bb0 = Bs[k8 * 256];
                float4 bb1 = Bs[k8 * 256 + 32];
                mma_tf32(acc[0][0], a0, bb0.x, bb0.y);
                mma_tf32(acc[0][1], a0, bb0.z, bb0.w);
                mma_tf32(acc[0][2], a0, bb1.x, bb1.y);
                mma_tf32(acc[0][3], a0, bb1.z, bb1.w);
                mma_tf32(acc[1][0], a1, bb0.x, bb0.y);
                mma_tf32(acc[1][1], a1, bb0.z, bb0.w);
                mma_tf32(acc[1][2], a1, bb1.x, bb1.y);
                mma_tf32(acc[1][3], a1, bb1.z, bb1.w);
            }
            // all lanes' LDS of stage g have completed (mma.sync is warp-wide);
            // release-arrive marks this warp done with the buffer
            if (lane == 0) mbar_arrive(mb_emp + 8u * (g & 3));

            // producer: prefetch stage g+3 once buffer (g+3)&3 is drained
            if (tid == 0) {
                int gp = g + 3;
                if (gp < 128) {
                    mbar_wait(mb_emp + 8u * (gp & 3), ((gp >> 2) & 1) ^ 1);
                    uint32_t mb = mb_full + 8u * (gp & 3);
                    mbar_expect_tx(mb, STAGE_BYTES);
                    bulk_g2s(bs_base + (uint32_t)(gp & 3) * STAGE_BYTES,
                             g_wp + (size_t)gp * 4096, STAGE_BYTES, mb);
                }
            }
        }

        // ---- epilogue: bias, online softmax partials, store raw logits
        const int n0 = nc * 128;
        float bias[8];
#pragma unroll
        for (int nt = 0; nt < 4; nt++) {
            bias[nt * 2]     = __ldg(b_out + n0 + wn * 32 + nt * 8 + 2 * cg);
            bias[nt * 2 + 1] = __ldg(b_out + n0 + wn * 32 + nt * 8 + 2 * cg + 1);
        }
#pragma unroll
        for (int mt = 0; mt < 2; mt++)
#pragma unroll
            for (int nt = 0; nt < 4; nt++) {
                acc[mt][nt][0] += bias[nt * 2];
                acc[mt][nt][1] += bias[nt * 2 + 1];
                acc[mt][nt][2] += bias[nt * 2];
                acc[mt][nt][3] += bias[nt * 2 + 1];
            }

#pragma unroll
        for (int mt = 0; mt < 2; mt++)
#pragma unroll
            for (int h = 0; h < 2; h++) {
                float m = -1e30f;
#pragma unroll
                for (int nt = 0; nt < 4; nt++) {
                    m = fmaxf(m, acc[mt][nt][2 * h]);
                    m = fmaxf(m, acc[mt][nt][2 * h + 1]);
                }
                m = fmaxf(m, __shfl_xor_sync(0xffffffffu, m, 1));
                m = fmaxf(m, __shfl_xor_sync(0xffffffffu, m, 2));
                float s = 0.f;
#pragma unroll
                for (int nt = 0; nt < 4; nt++) {
                    s += __expf(acc[mt][nt][2 * h] - m);
                    s += __expf(acc[mt][nt][2 * h + 1] - m);
                }
                s += __shfl_xor_sync(0xffffffffu, s, 1);
                s += __shfl_xor_sync(0xffffffffu, s, 2);
                if (cg == 0) {
                    int r = wm * 32 + mt * 16 + h * 8 + q;
                    sm[SM_PM + wn * 64 + r] = m;
                    sm[SM_PS + wn * 64 + r] = s;
                }
            }

#pragma unroll
        for (int mt = 0; mt < 2; mt++)
#pragma unroll
            for (int h = 0; h < 2; h++) {
                float* rp = rowp[mt][h] + n0 + wn * 32;
#pragma unroll
                for (int nt = 0; nt < 4; nt++) {
                    rp[nt * 8 + 2 * cg]     = acc[mt][nt][2 * h];
                    rp[nt * 8 + 2 * cg + 1] = acc[mt][nt][2 * h + 1];
                }
            }

        __syncthreads();
        if (tid < 64) {
            float m = sm[SM_M + tid], s = sm[SM_S + tid];
#pragma unroll
            for (int w = 0; w < 4; w++) {
                float mc = sm[SM_PM + w * 64 + tid];
                float sc = sm[SM_PS + w * 64 + tid];
                float mn = fmaxf(m, mc);
                s = s * __expf(m - mn) + sc * __expf(mc - mn);
                m = mn;
            }
            sm[SM_M + tid] = m;
            sm[SM_S + tid] = s;
        }
        __syncthreads();
    }

    // ---- col 1024 + final LSE
    if (tid < 64) {
        int r = tid;
        float v = sm[SM_D + r] + __ldg(b_out + 1024);
        float m = sm[SM_M + r], s = sm[SM_S + r];
        float mn = fmaxf(m, v);
        s = s * __expf(m - mn) + __expf(v - mn);
        float lse = mn + logf(s);
        sm[SM_LSE + r] = lse;
        int t = t0 + (r >> 3), u = u0 + (r & 7);
        out[(size_t)((b * T_ + t) * U_ + u) * NC_ + 1024] = v - lse;
    }
    __syncthreads();

    // ---- fixup: subtract LSE from cols 0..1023 (L2-hot)
    {
        const size_t base = (size_t)((b * T_ + t0) * U_ + u0) * NC_;
#pragma unroll 4
        for (int idx = tid; idx < 64 * 1024; idx += 256) {
            int r = idx >> 10, c = idx & 1023;
            float l = sm[SM_LSE + r];
            size_t off = base + (size_t)(r >> 3) * (U_ * NC_) + (size_t)(r & 7) * NC_ + c;
            out[off] -= l;
        }
    }
}

// ---------------------------------------------------------------------------
// launcher
// ---------------------------------------------------------------------------
extern "C" void kernel_launch(void* const* d_in, const int* in_sizes, int n_in,
                              void* d_out, int out_size) {
    const float* enc    = (const float*)d_in[0];
    const float* dec    = (const float*)d_in[1];
    const float* W_enc  = (const float*)d_in[2];
    const float* b_enc  = (const float*)d_in[3];
    const float* W_pred = (const float*)d_in[4];
    const float* b_pred = (const float*)d_in[5];
    const float* W_out  = (const float*)d_in[6];
    const float* b_out  = (const float*)d_in[7];
    float* out = (float*)d_out;

    void *pe = nullptr, *pp = nullptr;
    cudaGetSymbolAddress(&pe, g_e);
    cudaGetSymbolAddress(&pp, g_p);

    cudaFuncSetAttribute(joint_kernel, cudaFuncAttributeMaxDynamicSharedMemorySize,
                         SM_TOT * 4);

    pack_kernel<<<2048, 256>>>(W_out);
    proj_kernel<<<dim3(8, 16), 256>>>(enc, W_enc, b_enc, (float*)pe, T_, EH_);
    proj_kernel<<<dim3(8, 8), 256>>>(dec, W_pred, b_pred, (float*)pp, U_, PH_);

    dim3 grid(U_ / 8, T_ / 8, B_);   // (16, 32, 4) = 2048 blocks
    joint_kernel<<<grid, 256, SM_TOT * 4>>>(b_out, out);
}

// round 8
// speedup vs baseline: 1.5439x; 1.2213x over previous
#include <cuda_runtime.h>
#include <cstdint>

#define B_  4
#define T_  256
#define U_  128
#define EH_ 512
#define PH_ 320
#define JH_ 512
#define NC_ 1025

// ---------------------------------------------------------------------------
// scratch (no cudaMalloc allowed)
// ---------------------------------------------------------------------------
__device__ float g_e[B_ * T_ * JH_];     // [b*T+t][512]  e + b_enc
__device__ float g_p[B_ * U_ * JH_];     // [b*U+u][512]  p + b_pred
__device__ float g_wp[JH_ * 1024];       // W_out cols 0..1023, fragment-packed
__device__ float g_wl[JH_];              // W_out col 1024

// ---------------------------------------------------------------------------
// helpers
// ---------------------------------------------------------------------------
__device__ __forceinline__ void mma_tf32(float* c, const float4& a, float bx, float by) {
    const unsigned* au = reinterpret_cast<const unsigned*>(&a);
    unsigned b0 = __float_as_uint(bx), b1 = __float_as_uint(by);
    asm volatile(
        "mma.sync.aligned.m16n8k8.row.col.f32.tf32.tf32.f32 "
        "{%0,%1,%2,%3},{%4,%5,%6,%7},{%8,%9},{%0,%1,%2,%3};\n"
        : "+f"(c[0]), "+f"(c[1]), "+f"(c[2]), "+f"(c[3])
        : "r"(au[0]), "r"(au[1]), "r"(au[2]), "r"(au[3]), "r"(b0), "r"(b1));
}

__device__ __forceinline__ void mbar_init(uint32_t mbar, uint32_t count) {
    asm volatile("mbarrier.init.shared.b64 [%0], %1;\n" :: "r"(mbar), "r"(count) : "memory");
}
__device__ __forceinline__ void mbar_expect_tx(uint32_t mbar, uint32_t bytes) {
    asm volatile("mbarrier.arrive.expect_tx.shared.b64 _, [%0], %1;\n"
                 :: "r"(mbar), "r"(bytes) : "memory");
}
__device__ __forceinline__ void mbar_arrive(uint32_t mbar) {
    asm volatile("mbarrier.arrive.release.cta.shared::cta.b64 _, [%0];\n"
                 :: "r"(mbar) : "memory");
}
__device__ __forceinline__ void bulk_g2s(uint32_t dst, const void* src, uint32_t bytes,
                                         uint32_t mbar) {
    asm volatile(
        "cp.async.bulk.shared::cluster.global.mbarrier::complete_tx::bytes "
        "[%0], [%1], %2, [%3];\n"
        :: "r"(dst), "l"(src), "r"(bytes), "r"(mbar) : "memory");
}
__device__ __forceinline__ void mbar_wait(uint32_t mbar, uint32_t parity) {
    uint32_t done;
    asm volatile(
        "{\n\t.reg .pred p;\n\t"
        "mbarrier.try_wait.parity.acquire.cta.shared::cta.b64 p, [%1], %2;\n\t"
        "selp.b32 %0, 1, 0, p;\n\t}"
        : "=r"(done) : "r"(mbar), "r"(parity) : "memory");
    if (!done) {
        asm volatile(
            "{\n\t.reg .pred P1;\n\t"
            "W_%=:\n\t"
            "mbarrier.try_wait.parity.acquire.cta.shared::cta.b64 P1, [%0], %1, 0x989680;\n\t"
            "@P1 bra.uni D_%=;\n\t"
            "bra.uni W_%=;\n\t"
            "D_%=:\n\t}"
            :: "r"(mbar), "r"(parity) : "memory");
    }
}

// ---------------------------------------------------------------------------
// projection: O[row][j] = sum_h X[b][h][t] * W[h][j] + bias[j]
// ---------------------------------------------------------------------------
__global__ void __launch_bounds__(256)
proj_kernel(const float* __restrict__ X, const float* __restrict__ W,
            const float* __restrict__ bias, float* __restrict__ O,
            int L, int H) {
    __shared__ float Xs[16][64];
    __shared__ float Ws[16][64];
    int tid = threadIdx.x;
    int tc = tid & 15, tr = tid >> 4;
    int j0 = blockIdx.x * 64;
    int row0 = blockIdx.y * 64;
    int b = row0 / L;
    int t0 = row0 % L;

    float acc[4][4];
#pragma unroll
    for (int i = 0; i < 4; i++)
#pragma unroll
        for (int j = 0; j < 4; j++) acc[i][j] = 0.f;

    for (int k0 = 0; k0 < H; k0 += 16) {
#pragma unroll
        for (int i = 0; i < 4; i++) {
            int idx = tid + i * 256;
            int ky = idx >> 6, xx = idx & 63;
            Xs[ky][xx] = X[(size_t)(b * H + k0 + ky) * L + t0 + xx];
            Ws[ky][xx] = W[(size_t)(k0 + ky) * JH_ + j0 + xx];
        }
        __syncthreads();
#pragma unroll
        for (int k = 0; k < 16; k++) {
            float a[4], w[4];
#pragma unroll
            for (int i = 0; i < 4; i++) { a[i] = Xs[k][tr * 4 + i]; w[i] = Ws[k][tc * 4 + i]; }
#pragma unroll
            for (int i = 0; i < 4; i++)
#pragma unroll
                for (int j = 0; j < 4; j++) acc[i][j] += a[i] * w[j];
        }
        __syncthreads();
    }
#pragma unroll
    for (int i = 0; i < 4; i++)
#pragma unroll
        for (int j = 0; j < 4; j++) {
            int col = j0 + tc * 4 + j;
            O[(size_t)(row0 + tr * 4 + i) * JH_ + col] = acc[i][j] + bias[col];
        }
}

// ---------------------------------------------------------------------------
// pack W_out into mma-fragment order for 8 n-warps (n16 per warp):
// float index d bits: reg4[0:2) lane[2:7) wn[7:10) k8[10:12) kc[12:16) nc[16:19)
// j = kc*32 + k8*8 + (lane&3) + (reg4&1)*4
// c = nc*128 + wn*16 + (reg4>>1)*8 + (lane>>2)
// ---------------------------------------------------------------------------
__global__ void pack_kernel(const float* __restrict__ W) {
    int d = blockIdx.x * 256 + threadIdx.x;
    if (d < JH_ * 1024) {
        int reg4 = d & 3;
        int lane = (d >> 2) & 31;
        int wn   = (d >> 7) & 7;
        int k8   = (d >> 10) & 3;
        int kc   = (d >> 12) & 15;
        int nc   = d >> 16;
        int j = kc * 32 + k8 * 8 + (lane & 3) + (reg4 & 1) * 4;
        int c = nc * 128 + wn * 16 + (reg4 >> 1) * 8 + (lane >> 2);
        g_wp[d] = W[(size_t)j * NC_ + c];
    }
    if (d < JH_) g_wl[d] = W[(size_t)d * NC_ + 1024];
}

// ---------------------------------------------------------------------------
// joint kernel: 512 threads, 16 warps = 2(m) x 8(n), warp tile m32 x n16
// ---------------------------------------------------------------------------
#define SM_BS   32768                    // A fragments: 32768 floats (128 KB)
#define SM_WL   (SM_BS + 4 * 4096)       // 49152: w_l copy (512)
#define SM_M    (SM_WL + 512)            // 49664
#define SM_S    (SM_M + 64)              // 49728
#define SM_PM   (SM_S + 64)              // 49792 [8][64]
#define SM_PS   (SM_PM + 512)            // 50304 [8][64]
#define SM_D    (SM_PS + 512)            // 50816 col-1024 dots
#define SM_LSE  (SM_D + 64)              // 50880
#define SM_MBAR (SM_LSE + 64)            // 50944: 4 full + 4 empty (64 B)
#define SM_TOT  (SM_MBAR + 16)           // 50960 floats = 203840 B

#define STAGE_BYTES 16384u
#define NTHREADS 512

__global__ void __launch_bounds__(NTHREADS, 1)
joint_kernel(const float* __restrict__ b_out, float* __restrict__ out) {
    extern __shared__ float sm[];
    const int tid = threadIdx.x;
    const int lane = tid & 31, warp = tid >> 5;
    const int wm = warp & 1, wn = warp >> 1;      // 2 (m) x 8 (n)
    const int q = lane >> 2, cg = lane & 3;
    const int u0 = blockIdx.x * 8, t0 = blockIdx.y * 8, b = blockIdx.z;

    const uint32_t bs_base = (uint32_t)__cvta_generic_to_shared(sm + SM_BS);
    const uint32_t mb_full = (uint32_t)__cvta_generic_to_shared(sm + SM_MBAR);
    const uint32_t mb_emp  = mb_full + 32u;

    if (tid < 64) { sm[SM_M + tid] = -1e30f; sm[SM_S + tid] = 0.f; }
    sm[SM_WL + tid] = g_wl[tid];

    if (tid == 0) {
#pragma unroll
        for (int s = 0; s < 4; s++) {
            mbar_init(mb_full + 8u * s, 1);
            mbar_init(mb_emp + 8u * s, 16);    // one arrive per warp
        }
    }
    __syncthreads();
    // preload B stages 0..2 (overlap with A build)
    if (tid == 0) {
#pragma unroll
        for (int s = 0; s < 3; s++) {
            mbar_expect_tx(mb_full + 8u * s, STAGE_BYTES);
            bulk_g2s(bs_base + (uint32_t)s * STAGE_BYTES, g_wp + (size_t)s * 4096,
                     STAGE_BYTES, mb_full + 8u * s);
        }
    }

    // ---- build A in fragment order + accumulate col-1024 dot
    // float index i bits: reg[0:2) flane[2:7) m16[7:9) k8[9:15); i = k8g*512 + tid
    {
        const int reg   = tid & 3;
        const int flane = (tid >> 2) & 31;
        const int m16   = (tid >> 7) & 3;
        const int q_b   = flane >> 2;
        const int jo    = (flane & 3) + 4 * (reg >> 1);
        const int rl    = q_b + 8 * (reg & 1);
        const float* wl = sm + SM_WL;
        const float* pb = g_p + ((size_t)(b * U_ + u0 + q_b) << 9);
        const float* eb = g_e + ((size_t)(b * T_ + t0 + 2 * m16 + (reg & 1)) << 9);
        float d = 0.f;
#pragma unroll 8
        for (int k8g = 0; k8g < 64; k8g++) {
            int j = k8g * 8 + jo;
            float v = fmaxf(eb[j] + pb[j], 0.f);
            d += v * wl[j];
            unsigned uu; asm("cvt.rna.tf32.f32 %0,%1;" : "=r"(uu) : "f"(v));
            sm[k8g * 512 + tid] = __uint_as_float(uu);
        }
        d += __shfl_xor_sync(0xffffffffu, d, 2);
        d += __shfl_xor_sync(0xffffffffu, d, 4);
        d += __shfl_xor_sync(0xffffffffu, d, 8);
        if ((lane & 14) == 0) sm[SM_D + m16 * 16 + rl] = d;
    }
    __syncthreads();

    // per-thread output row pointers: rows r = wm*32 + mt*16 + h*8 + q
    float* rowp[2][2];
#pragma unroll
    for (int mt = 0; mt < 2; mt++)
#pragma unroll
        for (int h = 0; h < 2; h++) {
            int r = wm * 32 + mt * 16 + h * 8 + q;
            int t = t0 + (r >> 3), u = u0 + (r & 7);
            rowp[mt][h] = out + (size_t)((b * T_ + t) * U_ + u) * NC_;
        }

    const float4* Af = (const float4*)sm + (wm * 2) * 32 + lane;        // + kc*512 + k8*128 (+32 mt=1)
    const float4* Bbase = (const float4*)(sm + SM_BS) + wn * 32 + lane; // + stage*1024 + k8*256

    for (int nc = 0; nc < 8; nc++) {
        float acc[2][2][4];
#pragma unroll
        for (int mt = 0; mt < 2; mt++)
#pragma unroll
            for (int nt = 0; nt < 2; nt++)
#pragma unroll
                for (int i = 0; i < 4; i++) acc[mt][nt][i] = 0.f;

        for (int kc = 0; kc < 16; kc++) {
            const int g = nc * 16 + kc;
            mbar_wait(mb_full + 8u * (g & 3), (g >> 2) & 1);

            const float4* As = Af + (size_t)(kc * 4) * 128;
            const float4* Bs = Bbase + (size_t)(g & 3) * 1024;
#pragma unroll
            for (int k8 = 0; k8 < 4; k8++) {
                float4 a0 = As[k8 * 128];
                float4 a1 = As[k8 * 128 + 32];
                float4 bb = Bs[k8 * 256];
                mma_tf32(acc[0][0], a0, bb.x, bb.y);
                mma_tf32(acc[0][1], a0, bb.z, bb.w);
                mma_tf32(acc[1][0], a1, bb.x, bb.y);
                mma_tf32(acc[1][1], a1, bb.z, bb.w);
            }
            // mma.sync is warp-wide: all lanes' LDS of stage g completed
            if (lane == 0) mbar_arrive(mb_emp + 8u * (g & 3));

            if (tid == 0) {
                int gp = g + 3;
                if (gp < 128) {
                    mbar_wait(mb_emp + 8u * (gp & 3), ((gp >> 2) & 1) ^ 1);
                    uint32_t mb = mb_full + 8u * (gp & 3);
                    mbar_expect_tx(mb, STAGE_BYTES);
                    bulk_g2s(bs_base + (uint32_t)(gp & 3) * STAGE_BYTES,
                             g_wp + (size_t)gp * 4096, STAGE_BYTES, mb);
                }
            }
        }

        // ---- epilogue: bias, online softmax partials, store raw logits
        const int n0 = nc * 128;
        float bias[4];
#pragma unroll
        for (int nt = 0; nt < 2; nt++) {
            bias[nt * 2]     = __ldg(b_out + n0 + wn * 16 + nt * 8 + 2 * cg);
            bias[nt * 2 + 1] = __ldg(b_out + n0 + wn * 16 + nt * 8 + 2 * cg + 1);
        }
#pragma unroll
        for (int mt = 0; mt < 2; mt++)
#pragma unroll
            for (int nt = 0; nt < 2; nt++) {
                acc[mt][nt][0] += bias[nt * 2];
                acc[mt][nt][1] += bias[nt * 2 + 1];
                acc[mt][nt][2] += bias[nt * 2];
                acc[mt][nt][3] += bias[nt * 2 + 1];
            }

#pragma unroll
        for (int mt = 0; mt < 2; mt++)
#pragma unroll
            for (int h = 0; h < 2; h++) {
                float m = -1e30f;
#pragma unroll
                for (int nt = 0; nt < 2; nt++) {
                    m = fmaxf(m, acc[mt][nt][2 * h]);
                    m = fmaxf(m, acc[mt][nt][2 * h + 1]);
                }
                m = fmaxf(m, __shfl_xor_sync(0xffffffffu, m, 1));
                m = fmaxf(m, __shfl_xor_sync(0xffffffffu, m, 2));
                float s = 0.f;
#pragma unroll
                for (int nt = 0; nt < 2; nt++) {
                    s += __expf(acc[mt][nt][2 * h] - m);
                    s += __expf(acc[mt][nt][2 * h + 1] - m);
                }
                s += __shfl_xor_sync(0xffffffffu, s, 1);
                s += __shfl_xor_sync(0xffffffffu, s, 2);
                if (cg == 0) {
                    int r = wm * 32 + mt * 16 + h * 8 + q;
                    sm[SM_PM + wn * 64 + r] = m;
                    sm[SM_PS + wn * 64 + r] = s;
                }
            }

#pragma unroll
        for (int mt = 0; mt < 2; mt++)
#pragma unroll
            for (int h = 0; h < 2; h++) {
                float* rp = rowp[mt][h] + n0 + wn * 16;
#pragma unroll
                for (int nt = 0; nt < 2; nt++) {
                    rp[nt * 8 + 2 * cg]     = acc[mt][nt][2 * h];
                    rp[nt * 8 + 2 * cg + 1] = acc[mt][nt][2 * h + 1];
                }
            }

        __syncthreads();
        if (tid < 64) {
            float m = sm[SM_M + tid], s = sm[SM_S + tid];
#pragma unroll
            for (int w = 0; w < 8; w++) {
                float mc = sm[SM_PM + w * 64 + tid];
                float sc = sm[SM_PS + w * 64 + tid];
                float mn = fmaxf(m, mc);
                s = s * __expf(m - mn) + sc * __expf(mc - mn);
                m = mn;
            }
            sm[SM_M + tid] = m;
            sm[SM_S + tid] = s;
        }
        __syncthreads();
    }

    // ---- col 1024 + final LSE
    if (tid < 64) {
        int r = tid;
        float v = sm[SM_D + r] + __ldg(b_out + 1024);
        float m = sm[SM_M + r], s = sm[SM_S + r];
        float mn = fmaxf(m, v);
        s = s * __expf(m - mn) + __expf(v - mn);
        float lse = mn + logf(s);
        sm[SM_LSE + r] = lse;
        int t = t0 + (r >> 3), u = u0 + (r & 7);
        out[(size_t)((b * T_ + t) * U_ + u) * NC_ + 1024] = v - lse;
    }
    __syncthreads();

    // ---- fixup: subtract LSE from cols 0..1023 (L2-hot)
    {
        const size_t base = (size_t)((b * T_ + t0) * U_ + u0) * NC_;
#pragma unroll 4
        for (int idx = tid; idx < 64 * 1024; idx += NTHREADS) {
            int r = idx >> 10, c = idx & 1023;
            float l = sm[SM_LSE + r];
            size_t off = base + (size_t)(r >> 3) * (U_ * NC_) + (size_t)(r & 7) * NC_ + c;
            out[off] -= l;
        }
    }
}

// ---------------------------------------------------------------------------
// launcher
// ---------------------------------------------------------------------------
extern "C" void kernel_launch(void* const* d_in, const int* in_sizes, int n_in,
                              void* d_out, int out_size) {
    const float* enc    = (const float*)d_in[0];
    const float* dec    = (const float*)d_in[1];
    const float* W_enc  = (const float*)d_in[2];
    const float* b_enc  = (const float*)d_in[3];
    const float* W_pred = (const float*)d_in[4];
    const float* b_pred = (const float*)d_in[5];
    const float* W_out  = (const float*)d_in[6];
    const float* b_out  = (const float*)d_in[7];
    float* out = (float*)d_out;

    void *pe = nullptr, *pp = nullptr;
    cudaGetSymbolAddress(&pe, g_e);
    cudaGetSymbolAddress(&pp, g_p);

    cudaFuncSetAttribute(joint_kernel, cudaFuncAttributeMaxDynamicSharedMemorySize,
                         SM_TOT * 4);

    pack_kernel<<<2048, 256>>>(W_out);
    proj_kernel<<<dim3(8, 16), 256>>>(enc, W_enc, b_enc, (float*)pe, T_, EH_);
    proj_kernel<<<dim3(8, 8), 256>>>(dec, W_pred, b_pred, (float*)pp, U_, PH_);

    dim3 grid(U_ / 8, T_ / 8, B_);   // (16, 32, 4) = 2048 blocks
    joint_kernel<<<grid, NTHREADS, SM_TOT * 4>>>(b_out, out);
}

// round 10
// speedup vs baseline: 1.7395x; 1.1267x over previous
#include <cuda_runtime.h>
#include <cstdint>

#define B_  4
#define T_  256
#define U_  128
#define EH_ 512
#define PH_ 320
#define JH_ 512
#define NC_ 1025

// ---------------------------------------------------------------------------
// scratch (no cudaMalloc allowed)
// ---------------------------------------------------------------------------
__device__ float g_e[B_ * T_ * JH_];     // [b*T+t][512]  e + b_enc
__device__ float g_p[B_ * U_ * JH_];     // [b*U+u][512]  p + b_pred
__device__ float g_wp[JH_ * 1024];       // W_out cols 0..1023: 64 chunks of
                                         // [k32 x n256], fragment-packed
__device__ float g_wl[JH_];              // W_out col 1024

// ---------------------------------------------------------------------------
// helpers
// ---------------------------------------------------------------------------
__device__ __forceinline__ void mma_tf32(float* c, const float4& a, float bx, float by) {
    const unsigned* au = reinterpret_cast<const unsigned*>(&a);
    unsigned b0 = __float_as_uint(bx), b1 = __float_as_uint(by);
    asm volatile(
        "mma.sync.aligned.m16n8k8.row.col.f32.tf32.tf32.f32 "
        "{%0,%1,%2,%3},{%4,%5,%6,%7},{%8,%9},{%0,%1,%2,%3};\n"
        : "+f"(c[0]), "+f"(c[1]), "+f"(c[2]), "+f"(c[3])
        : "r"(au[0]), "r"(au[1]), "r"(au[2]), "r"(au[3]), "r"(b0), "r"(b1));
}

__device__ __forceinline__ void mbar_init(uint32_t mbar, uint32_t count) {
    asm volatile("mbarrier.init.shared.b64 [%0], %1;\n" :: "r"(mbar), "r"(count) : "memory");
}
__device__ __forceinline__ void mbar_expect_tx(uint32_t mbar, uint32_t bytes) {
    asm volatile("mbarrier.arrive.expect_tx.shared.b64 _, [%0], %1;\n"
                 :: "r"(mbar), "r"(bytes) : "memory");
}
__device__ __forceinline__ void mbar_arrive(uint32_t mbar) {
    asm volatile("mbarrier.arrive.release.cta.shared::cta.b64 _, [%0];\n"
                 :: "r"(mbar) : "memory");
}
__device__ __forceinline__ void bulk_g2s(uint32_t dst, const void* src, uint32_t bytes,
                                         uint32_t mbar) {
    asm volatile(
        "cp.async.bulk.shared::cluster.global.mbarrier::complete_tx::bytes "
        "[%0], [%1], %2, [%3];\n"
        :: "r"(dst), "l"(src), "r"(bytes), "r"(mbar) : "memory");
}
__device__ __forceinline__ void mbar_wait(uint32_t mbar, uint32_t parity) {
    uint32_t done;
    asm volatile(
        "{\n\t.reg .pred p;\n\t"
        "mbarrier.try_wait.parity.acquire.cta.shared::cta.b64 p, [%1], %2;\n\t"
        "selp.b32 %0, 1, 0, p;\n\t}"
        : "=r"(done) : "r"(mbar), "r"(parity) : "memory");
    if (!done) {
        asm volatile(
            "{\n\t.reg .pred P1;\n\t"
            "W_%=:\n\t"
            "mbarrier.try_wait.parity.acquire.cta.shared::cta.b64 P1, [%0], %1, 0x989680;\n\t"
            "@P1 bra.uni D_%=;\n\t"
            "bra.uni W_%=;\n\t"
            "D_%=:\n\t}"
            :: "r"(mbar), "r"(parity) : "memory");
    }
}

// ---------------------------------------------------------------------------
// projection: O[row][j] = sum_h X[b][h][t] * W[h][j] + bias[j]
// ---------------------------------------------------------------------------
__global__ void __launch_bounds__(256)
proj_kernel(const float* __restrict__ X, const float* __restrict__ W,
            const float* __restrict__ bias, float* __restrict__ O,
            int L, int H) {
    __shared__ float Xs[16][64];
    __shared__ float Ws[16][64];
    int tid = threadIdx.x;
    int tc = tid & 15, tr = tid >> 4;
    int j0 = blockIdx.x * 64;
    int row0 = blockIdx.y * 64;
    int b = row0 / L;
    int t0 = row0 % L;

    float acc[4][4];
#pragma unroll
    for (int i = 0; i < 4; i++)
#pragma unroll
        for (int j = 0; j < 4; j++) acc[i][j] = 0.f;

    for (int k0 = 0; k0 < H; k0 += 16) {
#pragma unroll
        for (int i = 0; i < 4; i++) {
            int idx = tid + i * 256;
            int ky = idx >> 6, xx = idx & 63;
            Xs[ky][xx] = X[(size_t)(b * H + k0 + ky) * L + t0 + xx];
            Ws[ky][xx] = W[(size_t)(k0 + ky) * JH_ + j0 + xx];
        }
        __syncthreads();
#pragma unroll
        for (int k = 0; k < 16; k++) {
            float a[4], w[4];
#pragma unroll
            for (int i = 0; i < 4; i++) { a[i] = Xs[k][tr * 4 + i]; w[i] = Ws[k][tc * 4 + i]; }
#pragma unroll
            for (int i = 0; i < 4; i++)
#pragma unroll
                for (int j = 0; j < 4; j++) acc[i][j] += a[i] * w[j];
        }
        __syncthreads();
    }
#pragma unroll
    for (int i = 0; i < 4; i++)
#pragma unroll
        for (int j = 0; j < 4; j++) {
            int col = j0 + tc * 4 + j;
            O[(size_t)(row0 + tr * 4 + i) * JH_ + col] = acc[i][j] + bias[col];
        }
}

// ---------------------------------------------------------------------------
// pack W_out into 64 chunks (g = nc*16 + kc) of [k32 x n256], fragment order:
// within-chunk float q bits: reg4[0:2) lane[2:7) sub[7] wn[8:11) k8[11:13)
// j = kc*32 + k8*8 + (lane&3) + (reg4&1)*4
// n = nc*256 + wn*32 + sub*16 + (reg4>>1)*8 + (lane>>2)
// ---------------------------------------------------------------------------
__global__ void pack_kernel(const float* __restrict__ W) {
    int d = blockIdx.x * 256 + threadIdx.x;
    if (d < JH_ * 1024) {
        int q = d & 8191;
        int chunk = d >> 13;
        int kc = chunk & 15, nc = chunk >> 4;
        int reg4 = q & 3;
        int lane = (q >> 2) & 31;
        int sub  = (q >> 7) & 1;
        int wn   = (q >> 8) & 7;
        int k8   = (q >> 11) & 3;
        int j = kc * 32 + k8 * 8 + (lane & 3) + (reg4 & 1) * 4;
        int n = nc * 256 + wn * 32 + sub * 16 + (reg4 >> 1) * 8 + (lane >> 2);
        g_wp[d] = W[(size_t)j * NC_ + n];
    }
    if (d < JH_) g_wl[d] = W[(size_t)d * NC_ + 1024];
}

// ---------------------------------------------------------------------------
// joint kernel: 512 threads, 16 warps = 2(m) x 8(n), warp tile m32 x n32,
// N in 4 chunks of 256, B 2-stage TMA pipeline (32 KB stages)
// ---------------------------------------------------------------------------
#define SM_BS   32768                    // A fragments: 32768 floats (128 KB)
#define SM_WL   (SM_BS + 2 * 8192)       // 49152: w_l copy (512)
#define SM_M    (SM_WL + 512)            // 49664
#define SM_S    (SM_M + 64)              // 49728
#define SM_PM   (SM_S + 64)              // 49792 [8][64]
#define SM_PS   (SM_PM + 512)            // 50304 [8][64]
#define SM_D    (SM_PS + 512)            // 50816 col-1024 dots
#define SM_LSE  (SM_D + 64)              // 50880
#define SM_MBAR (SM_LSE + 64)            // 50944: 2 full + 2 empty (32 B)
#define SM_TOT  (SM_MBAR + 8)            // 50952 floats = 203808 B

#define STAGE_BYTES 32768u
#define STAGE_F4    2048
#define NTHREADS 512

__global__ void __launch_bounds__(NTHREADS, 1)
joint_kernel(const float* __restrict__ b_out, float* __restrict__ out) {
    extern __shared__ float sm[];
    const int tid = threadIdx.x;
    const int lane = tid & 31, warp = tid >> 5;
    const int wm = warp & 1, wn = warp >> 1;      // 2 (m) x 8 (n)
    const int q = lane >> 2, cg = lane & 3;
    const int u0 = blockIdx.x * 8, t0 = blockIdx.y * 8, b = blockIdx.z;

    const uint32_t bs_base = (uint32_t)__cvta_generic_to_shared(sm + SM_BS);
    const uint32_t mb_full = (uint32_t)__cvta_generic_to_shared(sm + SM_MBAR);
    const uint32_t mb_emp  = mb_full + 16u;

    if (tid < 64) { sm[SM_M + tid] = -1e30f; sm[SM_S + tid] = 0.f; }
    sm[SM_WL + tid] = g_wl[tid];

    if (tid == 0) {
#pragma unroll
        for (int s = 0; s < 2; s++) {
            mbar_init(mb_full + 8u * s, 1);
            mbar_init(mb_emp + 8u * s, 16);    // one arrive per warp
        }
    }
    __syncthreads();
    // preload both stages (overlap with A build)
    if (tid == 0) {
#pragma unroll
        for (int s = 0; s < 2; s++) {
            mbar_expect_tx(mb_full + 8u * s, STAGE_BYTES);
            bulk_g2s(bs_base + (uint32_t)s * STAGE_BYTES, g_wp + (size_t)s * 8192,
                     STAGE_BYTES, mb_full + 8u * s);
        }
    }

    // ---- build A in fragment order + accumulate col-1024 dot
    // float index i bits: reg[0:2) flane[2:7) m16[7:9) k8[9:15); i = k8g*512 + tid
    {
        const int reg   = tid & 3;
        const int flane = (tid >> 2) & 31;
        const int m16   = (tid >> 7) & 3;
        const int q_b   = flane >> 2;
        const int jo    = (flane & 3) + 4 * (reg >> 1);
        const int rl    = q_b + 8 * (reg & 1);
        const float* wl = sm + SM_WL;
        const float* pb = g_p + ((size_t)(b * U_ + u0 + q_b) << 9);
        const float* eb = g_e + ((size_t)(b * T_ + t0 + 2 * m16 + (reg & 1)) << 9);
        float d = 0.f;
#pragma unroll 8
        for (int k8g = 0; k8g < 64; k8g++) {
            int j = k8g * 8 + jo;
            float v = fmaxf(eb[j] + pb[j], 0.f);
            d += v * wl[j];
            unsigned uu; asm("cvt.rna.tf32.f32 %0,%1;" : "=r"(uu) : "f"(v));
            sm[k8g * 512 + tid] = __uint_as_float(uu);
        }
        d += __shfl_xor_sync(0xffffffffu, d, 2);
        d += __shfl_xor_sync(0xffffffffu, d, 4);
        d += __shfl_xor_sync(0xffffffffu, d, 8);
        if ((lane & 14) == 0) sm[SM_D + m16 * 16 + rl] = d;
    }
    __syncthreads();

    // per-thread output row pointers: rows r = wm*32 + mt*16 + h*8 + q
    float* rowp[2][2];
#pragma unroll
    for (int mt = 0; mt < 2; mt++)
#pragma unroll
        for (int h = 0; h < 2; h++) {
            int r = wm * 32 + mt * 16 + h * 8 + q;
            int t = t0 + (r >> 3), u = u0 + (r & 7);
            rowp[mt][h] = out + (size_t)((b * T_ + t) * U_ + u) * NC_;
        }

    const float4* Af = (const float4*)sm + (wm * 2) * 32 + lane;        // +kc*512 +k8*128 (+32 mt=1)
    const float4* Bbase = (const float4*)(sm + SM_BS) + wn * 64 + lane; // +stage*2048 +k8*512 (+32 sub=1)

    for (int nc = 0; nc < 4; nc++) {
        float acc[2][4][4];   // [mt][nt = sub*2+pr][4]
#pragma unroll
        for (int mt = 0; mt < 2; mt++)
#pragma unroll
            for (int nt = 0; nt < 4; nt++)
#pragma unroll
                for (int i = 0; i < 4; i++) acc[mt][nt][i] = 0.f;

        for (int kc = 0; kc < 16; kc++) {
            const int g = nc * 16 + kc, s = g & 1;
            mbar_wait(mb_full + 8u * s, (g >> 1) & 1);

            const float4* As = Af + (size_t)(kc * 4) * 128;
            const float4* Bs = Bbase + (size_t)s * STAGE_F4;
#pragma unroll
            for (int k8 = 0; k8 < 4; k8++) {
                float4 a0 = As[k8 * 128];
                float4 a1 = As[k8 * 128 + 32];
                float4 b0 = Bs[k8 * 512];
                float4 b1 = Bs[k8 * 512 + 32];
                mma_tf32(acc[0][0], a0, b0.x, b0.y);
                mma_tf32(acc[0][1], a0, b0.z, b0.w);
                mma_tf32(acc[0][2], a0, b1.x, b1.y);
                mma_tf32(acc[0][3], a0, b1.z, b1.w);
                mma_tf32(acc[1][0], a1, b0.x, b0.y);
                mma_tf32(acc[1][1], a1, b0.z, b0.w);
                mma_tf32(acc[1][2], a1, b1.x, b1.y);
                mma_tf32(acc[1][3], a1, b1.z, b1.w);
            }
            // mma.sync is warp-wide: all lanes' LDS of stage s completed
            if (lane == 0) mbar_arrive(mb_emp + 8u * s);

            if (tid == 0) {
                int gp = g + 2;
                if (gp < 64) {
                    mbar_wait(mb_emp + 8u * (gp & 1), ((gp >> 1) + 1) & 1);
                    uint32_t mb = mb_full + 8u * (gp & 1);
                    mbar_expect_tx(mb, STAGE_BYTES);
                    bulk_g2s(bs_base + (uint32_t)(gp & 1) * STAGE_BYTES,
                             g_wp + (size_t)gp * 8192, STAGE_BYTES, mb);
                }
            }
        }

        // ---- epilogue: bias, online softmax partials, store raw logits
        const int n0 = nc * 256;
        float bias[8];
#pragma unroll
        for (int nt = 0; nt < 4; nt++) {
            bias[nt * 2]     = __ldg(b_out + n0 + wn * 32 + nt * 8 + 2 * cg);
            bias[nt * 2 + 1] = __ldg(b_out + n0 + wn * 32 + nt * 8 + 2 * cg + 1);
        }
#pragma unroll
        for (int mt = 0; mt < 2; mt++)
#pragma unroll
            for (int nt = 0; nt < 4; nt++) {
                acc[mt][nt][0] += bias[nt * 2];
                acc[mt][nt][1] += bias[nt * 2 + 1];
                acc[mt][nt][2] += bias[nt * 2];
                acc[mt][nt][3] += bias[nt * 2 + 1];
            }

#pragma unroll
        for (int mt = 0; mt < 2; mt++)
#pragma unroll
            for (int h = 0; h < 2; h++) {
                float m = -1e30f;
#pragma unroll
                for (int nt = 0; nt < 4; nt++) {
                    m = fmaxf(m, acc[mt][nt][2 * h]);
                    m = fmaxf(m, acc[mt][nt][2 * h + 1]);
                }
                m = fmaxf(m, __shfl_xor_sync(0xffffffffu, m, 1));
                m = fmaxf(m, __shfl_xor_sync(0xffffffffu, m, 2));
                float s = 0.f;
#pragma unroll
                for (int nt = 0; nt < 4; nt++) {
                    s += __expf(acc[mt][nt][2 * h] - m);
                    s += __expf(acc[mt][nt][2 * h + 1] - m);
                }
                s += __shfl_xor_sync(0xffffffffu, s, 1);
                s += __shfl_xor_sync(0xffffffffu, s, 2);
                if (cg == 0) {
                    int r = wm * 32 + mt * 16 + h * 8 + q;
                    sm[SM_PM + wn * 64 + r] = m;
                    sm[SM_PS + wn * 64 + r] = s;
                }
            }

#pragma unroll
        for (int mt = 0; mt < 2; mt++)
#pragma unroll
            for (int h = 0; h < 2; h++) {
                float* rp = rowp[mt][h] + n0 + wn * 32;
#pragma unroll
                for (int nt = 0; nt < 4; nt++) {
                    rp[nt * 8 + 2 * cg]     = acc[mt][nt][2 * h];
                    rp[nt * 8 + 2 * cg + 1] = acc[mt][nt][2 * h + 1];
                }
            }

        __syncthreads();
        if (tid < 64) {
            float m = sm[SM_M + tid], s = sm[SM_S + tid];
#pragma unroll
            for (int w = 0; w < 8; w++) {
                float mc = sm[SM_PM + w * 64 + tid];
                float sc = sm[SM_PS + w * 64 + tid];
                float mn = fmaxf(m, mc);
                s = s * __expf(m - mn) + sc * __expf(mc - mn);
                m = mn;
            }
            sm[SM_M + tid] = m;
            sm[SM_S + tid] = s;
        }
        __syncthreads();
    }

    // ---- col 1024 + final LSE
    if (tid < 64) {
        int r = tid;
        float v = sm[SM_D + r] + __ldg(b_out + 1024);
        float m = sm[SM_M + r], s = sm[SM_S + r];
        float mn = fmaxf(m, v);
        s = s * __expf(m - mn) + __expf(v - mn);
        float lse = mn + logf(s);
        sm[SM_LSE + r] = lse;
        int t = t0 + (r >> 3), u = u0 + (r & 7);
        out[(size_t)((b * T_ + t) * U_ + u) * NC_ + 1024] = v - lse;
    }
    __syncthreads();

    // ---- fixup: subtract LSE from cols 0..1023 (L2-hot)
    {
        const size_t base = (size_t)((b * T_ + t0) * U_ + u0) * NC_;
#pragma unroll 4
        for (int idx = tid; idx < 64 * 1024; idx += NTHREADS) {
            int r = idx >> 10, c = idx & 1023;
            float l = sm[SM_LSE + r];
            size_t off = base + (size_t)(r >> 3) * (U_ * NC_) + (size_t)(r & 7) * NC_ + c;
            out[off] -= l;
        }
    }
}

// ---------------------------------------------------------------------------
// launcher
// ---------------------------------------------------------------------------
extern "C" void kernel_launch(void* const* d_in, const int* in_sizes, int n_in,
                              void* d_out, int out_size) {
    const float* enc    = (const float*)d_in[0];
    const float* dec    = (const float*)d_in[1];
    const float* W_enc  = (const float*)d_in[2];
    const float* b_enc  = (const float*)d_in[3];
    const float* W_pred = (const float*)d_in[4];
    const float* b_pred = (const float*)d_in[5];
    const float* W_out  = (const float*)d_in[6];
    const float* b_out  = (const float*)d_in[7];
    float* out = (float*)d_out;

    void *pe = nullptr, *pp = nullptr;
    cudaGetSymbolAddress(&pe, g_e);
    cudaGetSymbolAddress(&pp, g_p);

    cudaFuncSetAttribute(joint_kernel, cudaFuncAttributeMaxDynamicSharedMemorySize,
                         SM_TOT * 4);

    pack_kernel<<<2048, 256>>>(W_out);
    proj_kernel<<<dim3(8, 16), 256>>>(enc, W_enc, b_enc, (float*)pe, T_, EH_);
    proj_kernel<<<dim3(8, 8), 256>>>(dec, W_pred, b_pred, (float*)pp, U_, PH_);

    dim3 grid(U_ / 8, T_ / 8, B_);   // (16, 32, 4) = 2048 blocks
    joint_kernel<<<grid, NTHREADS, SM_TOT * 4>>>(b_out, out);
}

// round 12
// speedup vs baseline: 1.7598x; 1.0116x over previous
#include <cuda_runtime.h>
#include <cstdint>

#define B_  4
#define T_  256
#define U_  128
#define EH_ 512
#define PH_ 320
#define JH_ 512
#define NC_ 1025

// ---------------------------------------------------------------------------
// scratch (no cudaMalloc allowed)
// ---------------------------------------------------------------------------
__device__ float g_e[B_ * T_ * JH_];          // [b*T+t][512]
__device__ float g_p[B_ * U_ * JH_];          // [b*U+u][512]
__device__ float g_wp[JH_ * 1024];            // W cols 0..1023, 64 chunks [k32 x n256]
__device__ float g_wl[JH_];                   // W col 1024
__device__ float g_h[(size_t)1024 * 65536];   // H fragment-packed: 268 MB
__device__ float g_d[1024 * 128];             // per-row col-1024 dots

// ---------------------------------------------------------------------------
// helpers
// ---------------------------------------------------------------------------
__device__ __forceinline__ void mma_tf32(float* c, const float4& a, float bx, float by) {
    const unsigned* au = reinterpret_cast<const unsigned*>(&a);
    unsigned b0 = __float_as_uint(bx), b1 = __float_as_uint(by);
    asm volatile(
        "mma.sync.aligned.m16n8k8.row.col.f32.tf32.tf32.f32 "
        "{%0,%1,%2,%3},{%4,%5,%6,%7},{%8,%9},{%0,%1,%2,%3};\n"
        : "+f"(c[0]), "+f"(c[1]), "+f"(c[2]), "+f"(c[3])
        : "r"(au[0]), "r"(au[1]), "r"(au[2]), "r"(au[3]), "r"(b0), "r"(b1));
}
__device__ __forceinline__ void mbar_init(uint32_t mbar, uint32_t count) {
    asm volatile("mbarrier.init.shared.b64 [%0], %1;\n" :: "r"(mbar), "r"(count) : "memory");
}
__device__ __forceinline__ void mbar_expect_tx(uint32_t mbar, uint32_t bytes) {
    asm volatile("mbarrier.arrive.expect_tx.shared.b64 _, [%0], %1;\n"
                 :: "r"(mbar), "r"(bytes) : "memory");
}
__device__ __forceinline__ void mbar_arrive(uint32_t mbar) {
    asm volatile("mbarrier.arrive.release.cta.shared::cta.b64 _, [%0];\n"
                 :: "r"(mbar) : "memory");
}
__device__ __forceinline__ void bulk_g2s(uint32_t dst, const void* src, uint32_t bytes,
                                         uint32_t mbar) {
    asm volatile(
        "cp.async.bulk.shared::cluster.global.mbarrier::complete_tx::bytes "
        "[%0], [%1], %2, [%3];\n"
        :: "r"(dst), "l"(src), "r"(bytes), "r"(mbar) : "memory");
}
__device__ __forceinline__ void mbar_wait(uint32_t mbar, uint32_t parity) {
    uint32_t done;
    asm volatile(
        "{\n\t.reg .pred p;\n\t"
        "mbarrier.try_wait.parity.acquire.cta.shared::cta.b64 p, [%1], %2;\n\t"
        "selp.b32 %0, 1, 0, p;\n\t}"
        : "=r"(done) : "r"(mbar), "r"(parity) : "memory");
    if (!done) {
        asm volatile(
            "{\n\t.reg .pred P1;\n\t"
            "W_%=:\n\t"
            "mbarrier.try_wait.parity.acquire.cta.shared::cta.b64 P1, [%0], %1, 0x989680;\n\t"
            "@P1 bra.uni D_%=;\n\t"
            "bra.uni W_%=;\n\t"
            "D_%=:\n\t}"
            :: "r"(mbar), "r"(parity) : "memory");
    }
}

// ---------------------------------------------------------------------------
// projection: O[row][j] = sum_h X[b][h][t] * W[h][j] + bias[j]
// ---------------------------------------------------------------------------
__global__ void __launch_bounds__(256)
proj_kernel(const float* __restrict__ X, const float* __restrict__ W,
            const float* __restrict__ bias, float* __restrict__ O,
            int L, int H) {
    __shared__ float Xs[16][64];
    __shared__ float Ws[16][64];
    int tid = threadIdx.x;
    int tc = tid & 15, tr = tid >> 4;
    int j0 = blockIdx.x * 64;
    int row0 = blockIdx.y * 64;
    int b = row0 / L;
    int t0 = row0 % L;

    float acc[4][4];
#pragma unroll
    for (int i = 0; i < 4; i++)
#pragma unroll
        for (int j = 0; j < 4; j++) acc[i][j] = 0.f;

    for (int k0 = 0; k0 < H; k0 += 16) {
#pragma unroll
        for (int i = 0; i < 4; i++) {
            int idx = tid + i * 256;
            int ky = idx >> 6, xx = idx & 63;
            Xs[ky][xx] = X[(size_t)(b * H + k0 + ky) * L + t0 + xx];
            Ws[ky][xx] = W[(size_t)(k0 + ky) * JH_ + j0 + xx];
        }
        __syncthreads();
#pragma unroll
        for (int k = 0; k < 16; k++) {
            float a[4], w[4];
#pragma unroll
            for (int i = 0; i < 4; i++) { a[i] = Xs[k][tr * 4 + i]; w[i] = Ws[k][tc * 4 + i]; }
#pragma unroll
            for (int i = 0; i < 4; i++)
#pragma unroll
                for (int j = 0; j < 4; j++) acc[i][j] += a[i] * w[j];
        }
        __syncthreads();
    }
#pragma unroll
    for (int i = 0; i < 4; i++)
#pragma unroll
        for (int j = 0; j < 4; j++) {
            int col = j0 + tc * 4 + j;
            O[(size_t)(row0 + tr * 4 + i) * JH_ + col] = acc[i][j] + bias[col];
        }
}

// ---------------------------------------------------------------------------
// pack W_out: 64 chunks (g = nc*16 + kc) of [k32 x n256] fragment order:
// q bits: reg4[0:2) lane[2:7) quad[7:9) wn[9:11) k8[11:13)
// j = kc*32 + k8*8 + (lane&3) + (reg4&1)*4
// n = nc*256 + wn*64 + quad*16 + (reg4>>1)*8 + (lane>>2)
// ---------------------------------------------------------------------------
__global__ void pack_kernel(const float* __restrict__ W) {
    int d = blockIdx.x * 256 + threadIdx.x;
    if (d < JH_ * 1024) {
        int q = d & 8191;
        int chunk = d >> 13;
        int kc = chunk & 15, nc = chunk >> 4;
        int reg4 = q & 3;
        int lane = (q >> 2) & 31;
        int quad = (q >> 7) & 3;
        int wn   = (q >> 9) & 3;
        int k8   = (q >> 11) & 3;
        int j = kc * 32 + k8 * 8 + (lane & 3) + (reg4 & 1) * 4;
        int n = nc * 256 + wn * 64 + quad * 16 + (reg4 >> 1) * 8 + (lane >> 2);
        g_wp[d] = W[(size_t)j * NC_ + n];
    }
    if (d < JH_) g_wl[d] = W[(size_t)d * NC_ + 1024];
}

// ---------------------------------------------------------------------------
// build H: per block (bIdx) 128 rows (16t x 8u), K=512, fragment-packed to g_h
// as 16 chunks of [m128 x k32] (4096 floats). i bits within chunk:
//   reg[0:2) lane[2:7) mt[7] wm[8:10) k8[10:12)
//   row = wm*32 + mt*16 + (lane>>2) + 8*(reg&1);  k = k8*8 + (lane&3) + 4*(reg>>1)
// Also folds col-1024 dot into g_d[bIdx*128 + row].
// ---------------------------------------------------------------------------
__global__ void __launch_bounds__(512)
build_kernel() {
    __shared__ float es[16 * 33];
    __shared__ float ps[8 * 33];
    __shared__ float wls[512];
    __shared__ float sd[128];
    const int tid = threadIdx.x;
    const int u0 = blockIdx.x * 8, t0 = blockIdx.y * 16, bb = blockIdx.z;
    const int bIdx = (bb * 16 + blockIdx.y) * 16 + blockIdx.x;

    wls[tid] = g_wl[tid];
    if (tid < 128) sd[tid] = 0.f;

    // per-thread fixed decode (tid bits) + per-it parity bits
    const int reg  = tid & 3;
    const int lane = (tid >> 2) & 31;
    const int mt   = (tid >> 7) & 1;
    const int wml  = (tid >> 8) & 1;
    const int rbase = mt * 16 + (lane >> 2) + 8 * (reg & 1);
    float d2[2] = {0.f, 0.f};

    for (int kc = 0; kc < 16; kc++) {
        __syncthreads();
        {
            int row = tid >> 5, k = tid & 31;
            es[row * 33 + k] = g_e[(size_t)(bb * T_ + t0 + row) * JH_ + kc * 32 + k];
            if (tid < 256)
                ps[row * 33 + k] = g_p[(size_t)(bb * U_ + u0 + row) * JH_ + kc * 32 + k];
        }
        __syncthreads();
        float* dst = g_h + (size_t)(bIdx * 16 + kc) * 4096;
#pragma unroll
        for (int it = 0; it < 8; it++) {
            int wm = wml + 2 * (it & 1);
            int k8 = it >> 1;
            int row = wm * 32 + rbase;
            int kk = k8 * 8 + (lane & 3) + 4 * (reg >> 1);
            float v = fmaxf(es[(row >> 3) * 33 + kk] + ps[(row & 7) * 33 + kk], 0.f);
            d2[it & 1] += v * wls[kc * 32 + kk];
            unsigned uu; asm("cvt.rna.tf32.f32 %0,%1;" : "=r"(uu) : "f"(v));
            dst[it * 512 + tid] = __uint_as_float(uu);
        }
    }
    __syncthreads();
    atomicAdd(&sd[wml * 32 + rbase], d2[0]);
    atomicAdd(&sd[(wml + 2) * 32 + rbase], d2[1]);
    __syncthreads();
    if (tid < 128) g_d[bIdx * 128 + tid] = sd[tid];
}

// ---------------------------------------------------------------------------
// joint: pure streamed GEMM. M=128, N 4 chunks of 256, K 16 chunks of 32.
// 512 threads = 16 warps = 4(m) x 4(n); warp tile m32 x n64 (64 acc regs).
// 4-stage pipeline, 48 KB/stage (A 16 KB + B 32 KB), TMA bulk.
// ---------------------------------------------------------------------------
#define S_M   49152
#define S_S   49280
#define S_PM  49408   /* [4][128] */
#define S_PS  49920   /* [4][128] */
#define S_LSE 50432
#define S_MB  50560   /* 8 mbarriers (64 B) */
#define SM_TOT 50576  /* floats = 202304 B */

__global__ void __launch_bounds__(512, 1)
joint_kernel(const float* __restrict__ b_out, float* __restrict__ out) {
    extern __shared__ float sm[];
    const int tid = threadIdx.x;
    const int lane = tid & 31, warp = tid >> 5;
    const int wm = warp & 3, wn = warp >> 2;      // 4 (m) x 4 (n)
    const int q = lane >> 2, cg = lane & 3;
    const int u0 = blockIdx.x * 8, t0 = blockIdx.y * 16, bb = blockIdx.z;
    const int bIdx = (bb * 16 + blockIdx.y) * 16 + blockIdx.x;

    const uint32_t smu = (uint32_t)__cvta_generic_to_shared(sm);
    const uint32_t mb_full = (uint32_t)__cvta_generic_to_shared(sm + S_MB);
    const uint32_t mb_emp  = mb_full + 32u;

    if (tid < 128) { sm[S_M + tid] = -1e30f; sm[S_S + tid] = 0.f; }
    if (tid == 0) {
#pragma unroll
        for (int s = 0; s < 4; s++) {
            mbar_init(mb_full + 8u * s, 1);
            mbar_init(mb_emp + 8u * s, 16);
        }
    }
    __syncthreads();
    if (tid == 0) {
#pragma unroll
        for (int g0 = 0; g0 < 4; g0++) {
            uint32_t mb = mb_full + 8u * g0;
            mbar_expect_tx(mb, 49152u);
            bulk_g2s(smu + (uint32_t)g0 * 16384u,
                     g_h + (size_t)(bIdx * 16 + g0) * 4096, 16384u, mb);
            bulk_g2s(smu + 65536u + (uint32_t)g0 * 32768u,
                     g_wp + (size_t)g0 * 8192, 32768u, mb);
        }
    }

    // per-thread output row pointers: rows r = wm*32 + mt*16 + h*8 + q
    float* rowp[2][2];
#pragma unroll
    for (int mt = 0; mt < 2; mt++)
#pragma unroll
        for (int h = 0; h < 2; h++) {
            int r = wm * 32 + mt * 16 + h * 8 + q;
            int t = t0 + (r >> 3), u = u0 + (r & 7);
            rowp[mt][h] = out + (size_t)((bb * T_ + t) * U_ + u) * NC_;
        }

    const float4* Abase = (const float4*)sm + wm * 64 + lane;           // + s*1024 + mt*32 + k8*256
    const float4* Bbase = (const float4*)sm + 4096 + wn * 128 + lane;   // + s*2048 + quad*32 + k8*512

    for (int nc = 0; nc < 4; nc++) {
        float acc[2][8][4];
#pragma unroll
        for (int mt = 0; mt < 2; mt++)
#pragma unroll
            for (int nt = 0; nt < 8; nt++)
#pragma unroll
                for (int i = 0; i < 4; i++) acc[mt][nt][i] = 0.f;

        for (int kc = 0; kc < 16; kc++) {
            const int g = nc * 16 + kc, s = g & 3;
            mbar_wait(mb_full + 8u * s, (g >> 2) & 1);

            const float4* As = Abase + (size_t)s * 1024;
            const float4* Bs = Bbase + (size_t)s * 2048;
#pragma unroll
            for (int k8 = 0; k8 < 4; k8++) {
                float4 a0 = As[k8 * 256];
                float4 a1 = As[k8 * 256 + 32];
#pragma unroll
                for (int quad = 0; quad < 4; quad++) {
                    float4 bq = Bs[quad * 32 + k8 * 512];
                    mma_tf32(acc[0][quad * 2],     a0, bq.x, bq.y);
                    mma_tf32(acc[0][quad * 2 + 1], a0, bq.z, bq.w);
                    mma_tf32(acc[1][quad * 2],     a1, bq.x, bq.y);
                    mma_tf32(acc[1][quad * 2 + 1], a1, bq.z, bq.w);
                }
            }
            if (lane == 0) mbar_arrive(mb_emp + 8u * s);

            if (tid == 0) {
                int gp = g + 4;
                if (gp < 64) {
                    int sp = gp & 3;
                    mbar_wait(mb_emp + 8u * sp, ((gp >> 2) + 1) & 1);
                    uint32_t mb = mb_full + 8u * sp;
                    mbar_expect_tx(mb, 49152u);
                    bulk_g2s(smu + (uint32_t)sp * 16384u,
                             g_h + (size_t)(bIdx * 16 + (gp & 15)) * 4096, 16384u, mb);
                    bulk_g2s(smu + 65536u + (uint32_t)sp * 32768u,
                             g_wp + (size_t)gp * 8192, 32768u, mb);
                }
            }
        }

        // ---- epilogue: bias, online stats, raw logit stores
        const int n0 = nc * 256;
#pragma unroll
        for (int nt = 0; nt < 8; nt++) {
            int off = n0 + wn * 64 + (nt >> 1) * 16 + (nt & 1) * 8 + 2 * cg;
            float b0 = __ldg(b_out + off);
            float b1 = __ldg(b_out + off + 1);
#pragma unroll
            for (int mt = 0; mt < 2; mt++) {
                acc[mt][nt][0] += b0;
                acc[mt][nt][1] += b1;
                acc[mt][nt][2] += b0;
                acc[mt][nt][3] += b1;
            }
        }

#pragma unroll
        for (int mt = 0; mt < 2; mt++)
#pragma unroll
            for (int h = 0; h < 2; h++) {
                float m = -1e30f;
#pragma unroll
                for (int nt = 0; nt < 8; nt++) {
                    m = fmaxf(m, acc[mt][nt][2 * h]);
                    m = fmaxf(m, acc[mt][nt][2 * h + 1]);
                }
                m = fmaxf(m, __shfl_xor_sync(0xffffffffu, m, 1));
                m = fmaxf(m, __shfl_xor_sync(0xffffffffu, m, 2));
                float s = 0.f;
#pragma unroll
                for (int nt = 0; nt < 8; nt++) {
                    s += __expf(acc[mt][nt][2 * h] - m);
                    s += __expf(acc[mt][nt][2 * h + 1] - m);
                }
                s += __shfl_xor_sync(0xffffffffu, s, 1);
                s += __shfl_xor_sync(0xffffffffu, s, 2);
                if (cg == 0) {
                    int r = wm * 32 + mt * 16 + h * 8 + q;
                    sm[S_PM + wn * 128 + r] = m;
                    sm[S_PS + wn * 128 + r] = s;
                }
            }

#pragma unroll
        for (int mt = 0; mt < 2; mt++)
#pragma unroll
            for (int h = 0; h < 2; h++) {
                float* rp = rowp[mt][h] + n0 + wn * 64;
#pragma unroll
                for (int nt = 0; nt < 8; nt++) {
                    int off = (nt >> 1) * 16 + (nt & 1) * 8 + 2 * cg;
                    rp[off]     = acc[mt][nt][2 * h];
                    rp[off + 1] = acc[mt][nt][2 * h + 1];
                }
            }

        __syncthreads();
        if (tid < 128) {
            float m = sm[S_M + tid], s = sm[S_S + tid];
#pragma unroll
            for (int w = 0; w < 4; w++) {
                float mc = sm[S_PM + w * 128 + tid];
                float sc = sm[S_PS + w * 128 + tid];
                float mn = fmaxf(m, mc);
                s = s * __expf(m - mn) + sc * __expf(mc - mn);
                m = mn;
            }
            sm[S_M + tid] = m;
            sm[S_S + tid] = s;
        }
        __syncthreads();
    }

    // ---- col 1024 + final LSE
    if (tid < 128) {
        int r = tid;
        float v = g_d[bIdx * 128 + r] + __ldg(b_out + 1024);
        float m = sm[S_M + r], s = sm[S_S + r];
        float mn = fmaxf(m, v);
        s = s * __expf(m - mn) + __expf(v - mn);
        float lse = mn + logf(s);
        sm[S_LSE + r] = lse;
        int t = t0 + (r >> 3), u = u0 + (r & 7);
        out[(size_t)((bb * T_ + t) * U_ + u) * NC_ + 1024] = v - lse;
    }
    __syncthreads();

    // ---- fixup: subtract LSE from cols 0..1023 (L2-hot)
#pragma unroll 4
    for (int idx = tid; idx < 128 * 1024; idx += 512) {
        int r = idx >> 10, c = idx & 1023;
        int t = t0 + (r >> 3), u = u0 + (r & 7);
        out[(size_t)((bb * T_ + t) * U_ + u) * NC_ + c] -= sm[S_LSE + r];
    }
}

// ---------------------------------------------------------------------------
// launcher
// ---------------------------------------------------------------------------
extern "C" void kernel_launch(void* const* d_in, const int* in_sizes, int n_in,
                              void* d_out, int out_size) {
    const float* enc    = (const float*)d_in[0];
    const float* dec    = (const float*)d_in[1];
    const float* W_enc  = (const float*)d_in[2];
    const float* b_enc  = (const float*)d_in[3];
    const float* W_pred = (const float*)d_in[4];
    const float* b_pred = (const float*)d_in[5];
    const float* W_out  = (const float*)d_in[6];
    const float* b_out  = (const float*)d_in[7];
    float* out = (float*)d_out;

    void *pe = nullptr, *pp = nullptr;
    cudaGetSymbolAddress(&pe, g_e);
    cudaGetSymbolAddress(&pp, g_p);

    cudaFuncSetAttribute(joint_kernel, cudaFuncAttributeMaxDynamicSharedMemorySize,
                         SM_TOT * 4);

    pack_kernel<<<2048, 256>>>(W_out);
    proj_kernel<<<dim3(8, 16), 256>>>(enc, W_enc, b_enc, (float*)pe, T_, EH_);
    proj_kernel<<<dim3(8, 8), 256>>>(dec, W_pred, b_pred, (float*)pp, U_, PH_);

    dim3 grid(U_ / 8, T_ / 16, B_);   // (16, 16, 4) = 1024 blocks, 128 rows each
    build_kernel<<<grid, 512>>>();
    joint_kernel<<<grid, 512, SM_TOT * 4>>>(b_out, out);
}